// round 11
// baseline (speedup 1.0000x reference)
#include <cuda_runtime.h>
#include <cuda_fp16.h>
#include <cstdint>
#include <cstddef>

#define LR_C   0.001f
#define TAU_C  1000.0f

// GEMM tiling: 128x128 CTA tile, 4 warps (2x2), warp tile 64x64, fp16 BKT=64
#define BM 128
#define BN 128
#define BKT 64
#define NSTAGES 3
#define A_BYTES (BM * 128)                   // 16 KB (128 rows x 64 halves)
#define STAGE_BYTES (2 * A_BYTES)            // 32 KB
#define SMEM_TOTAL (NSTAGES * STAGE_BYTES)   // 96 KB -> 2 CTA/SM
#define RSPLIT 64                            // = DIM_B / BM

// Fixed problem shape: B=8192, IN=OUT=4096.
#define DIM_B   8192
#define DIM_IO  4096

// Scratch (__device__ globals: the sanctioned alloc-free workaround)
__device__ __half g_xr[(size_t)DIM_B * DIM_IO];   // rn(x)            B x IN
__device__ __half g_wr[(size_t)DIM_IO * DIM_IO];  // rn(w)            OUT x IN
__device__ __half g_xt[(size_t)DIM_IO * DIM_B];   // rn(x)^T          IN x B
__device__ __half g_pt[(size_t)DIM_IO * DIM_B];   // rn(relu(o-th))^T OUT x B
__device__ float  g_partial[RSPLIT * DIM_IO];

// ---------------------------------------------------------------------------
// PTX helpers (baseline sm_80+ features ONLY)
// ---------------------------------------------------------------------------
__device__ __forceinline__ uint32_t smem_u32(const void* p) {
    return (uint32_t)__cvta_generic_to_shared(p);
}

__device__ __forceinline__ void cp_async16(uint32_t s, const void* g) {
    asm volatile("cp.async.cg.shared.global [%0], [%1], 16;\n" :: "r"(s), "l"(g));
}
#define CP_COMMIT() asm volatile("cp.async.commit_group;\n" ::)
#define CP_WAIT1()  asm volatile("cp.async.wait_group 1;\n" ::: "memory")

__device__ __forceinline__ void ldsm_x4(uint32_t* r, uint32_t addr) {
    asm volatile("ldmatrix.sync.aligned.m8n8.x4.shared.b16 {%0,%1,%2,%3}, [%4];"
                 : "=r"(r[0]), "=r"(r[1]), "=r"(r[2]), "=r"(r[3]) : "r"(addr));
}

__device__ __forceinline__ uint32_t sw128(uint32_t off) {
    return off ^ ((off >> 3) & 0x70);
}

// m16n8k16 fp16 MMA, fp32 accumulate
__device__ __forceinline__ void mma_16816(float* c, const uint32_t* a,
                                          uint32_t b0, uint32_t b1) {
    asm volatile(
        "mma.sync.aligned.m16n8k16.row.col.f32.f16.f16.f32 "
        "{%0,%1,%2,%3}, {%4,%5,%6,%7}, {%8,%9}, {%0,%1,%2,%3};"
        : "+f"(c[0]), "+f"(c[1]), "+f"(c[2]), "+f"(c[3])
        : "r"(a[0]), "r"(a[1]), "r"(a[2]), "r"(a[3]), "r"(b0), "r"(b1));
}

// ---------------------------------------------------------------------------
// FP16 tensor-core GEMM: C[M,N] = A[M,K] * B[N,K]^T (both K-major half)
// mode 0: C = D, and fused per-CTA column sums -> g_partial[blockIdx.y][col]
// mode 1: C = Wold + scale * D
// SMEM layout: 128 rows x 128 bytes (64 halves = one BKT slice), SW128 swizzle.
// ---------------------------------------------------------------------------
__device__ __forceinline__ void load_stage(uint32_t smem_base, int stage,
                                           const __half* Ab, const __half* Bb,
                                           int K, int k0, int tid) {
    uint32_t sa = smem_base + stage * STAGE_BYTES;
    uint32_t sb = sa + A_BYTES;
    #pragma unroll
    for (int i = 0; i < 8; i++) {            // A: 128 rows x 8 x 16B chunks
        int idx = tid + i * 128;
        int row = idx >> 3, c = idx & 7;
        cp_async16(sa + sw128((uint32_t)(row * 128 + c * 16)),
                   (const char*)(Ab + (size_t)row * K + k0) + c * 16);
    }
    #pragma unroll
    for (int i = 0; i < 8; i++) {            // B: 128 rows x 8 x 16B chunks
        int idx = tid + i * 128;
        int row = idx >> 3, c = idx & 7;
        cp_async16(sb + sw128((uint32_t)(row * 128 + c * 16)),
                   (const char*)(Bb + (size_t)row * K + k0) + c * 16);
    }
}

__global__ __launch_bounds__(128, 2) void gemm_mma_kernel(
    const __half* __restrict__ A, const __half* __restrict__ Bmat,
    const float* __restrict__ Wold, float* __restrict__ C,
    int M, int N, int K, float scale, int mode)
{
    extern __shared__ char smem[];
    const uint32_t smem_base = smem_u32(smem);
    const int tid  = threadIdx.x;
    const int warp = tid >> 5, lane = tid & 31;
    const int wm = warp >> 1, wn = warp & 1;       // 2 x 2 warp grid, 64x64 each
    const int lr = lane >> 2, lc = lane & 3;

    const int mbase = blockIdx.y * BM;
    const int nbase = blockIdx.x * BN;
    const __half* Ab = A + (size_t)mbase * K;
    const __half* Bb = Bmat + (size_t)nbase * K;

    // ldmatrix addressing (128B smem rows, 16B chunks, swizzle mask (lane&7)<<4)
    const uint32_t swz_mask = (uint32_t)((lane & 7) << 4);
    const int arow = wm * 64 + ((lane >> 3) & 1) * 8 + (lane & 7);
    const uint32_t a_kb = (uint32_t)((lane >> 4) * 16);
    uint32_t a_rowoff[4];
    #pragma unroll
    for (int mt = 0; mt < 4; mt++) a_rowoff[mt] = (uint32_t)((arow + mt * 16) * 128);
    const int brow = wn * 64 + ((lane >> 4) & 1) * 8 + (lane & 7);
    const uint32_t b_kb = (uint32_t)(((lane >> 3) & 1) * 16);
    uint32_t b_rowoff[4];
    #pragma unroll
    for (int p = 0; p < 4; p++) b_rowoff[p] = (uint32_t)((brow + p * 16) * 128);

    float acc[4][8][4];                            // [mt][nt][frag]
    #pragma unroll
    for (int i = 0; i < 4; i++)
        #pragma unroll
        for (int j = 0; j < 8; j++)
            #pragma unroll
            for (int f = 0; f < 4; f++) acc[i][j][f] = 0.f;

    const int niter = K / BKT;

    load_stage(smem_base, 0, Ab, Bb, K, 0, tid);   CP_COMMIT();
    load_stage(smem_base, 1, Ab, Bb, K, BKT, tid); CP_COMMIT();

    // Fragment double buffer: load ks+1 while issuing MMAs of ks.
    uint32_t a[2][4][4], b[2][4][4];

    int buf = 0;
    for (int it = 0; it < niter; ++it) {
        CP_WAIT1();
        __syncthreads();
        uint32_t sa = smem_base + buf * STAGE_BYTES;
        uint32_t sb = sa + A_BYTES;

        // Issue next stage's cp.async EARLY so DMA overlaps the whole MMA block.
        // Stage (it+2)%3 was last read at iteration it-1; the bar above orders
        // those shared reads before these writes.
        const int itn = it + 2;
        if (itn < niter)
            load_stage(smem_base, itn % NSTAGES, Ab, Bb, K, itn * BKT, tid);
        CP_COMMIT();

        // prime ks = 0
        {
            const uint32_t xa = a_kb ^ swz_mask;
            const uint32_t xb = b_kb ^ swz_mask;
            #pragma unroll
            for (int mt = 0; mt < 4; mt++) ldsm_x4(a[0][mt], sa + a_rowoff[mt] + xa);
            #pragma unroll
            for (int p = 0; p < 4; p++)    ldsm_x4(b[0][p], sb + b_rowoff[p] + xb);
        }

        #pragma unroll
        for (int ks = 0; ks < BKT / 16; ks++) {    // 4 k16-steps, 32B stride each
            const int cur = ks & 1, nxt = cur ^ 1;
            if (ks < BKT / 16 - 1) {               // prefetch next fragments
                const uint32_t xa = ((uint32_t)((ks + 1) * 32) + a_kb) ^ swz_mask;
                const uint32_t xb = ((uint32_t)((ks + 1) * 32) + b_kb) ^ swz_mask;
                #pragma unroll
                for (int mt = 0; mt < 4; mt++) ldsm_x4(a[nxt][mt], sa + a_rowoff[mt] + xa);
                #pragma unroll
                for (int p = 0; p < 4; p++)    ldsm_x4(b[nxt][p], sb + b_rowoff[p] + xb);
            }
            #pragma unroll
            for (int mt = 0; mt < 4; mt++) {
                #pragma unroll
                for (int p = 0; p < 4; p++) {
                    mma_16816(acc[mt][2 * p],     a[cur][mt], b[cur][p][0], b[cur][p][1]);
                    mma_16816(acc[mt][2 * p + 1], a[cur][mt], b[cur][p][2], b[cur][p][3]);
                }
            }
        }

        buf = (buf + 1 == NSTAGES) ? 0 : buf + 1;
    }

    // Epilogue: per thread 4x8 tiles, two float2 rows each
    #pragma unroll
    for (int mt = 0; mt < 4; mt++) {
        int r0 = mbase + wm * 64 + mt * 16 + lr;
        #pragma unroll
        for (int nt = 0; nt < 8; nt++) {
            int cc = nbase + wn * 64 + nt * 8 + lc * 2;
            size_t i0 = (size_t)r0 * N + cc;
            size_t i1 = (size_t)(r0 + 8) * N + cc;
            if (mode == 0) {
                *(float2*)(C + i0) = make_float2(acc[mt][nt][0], acc[mt][nt][1]);
                *(float2*)(C + i1) = make_float2(acc[mt][nt][2], acc[mt][nt][3]);
            } else {
                float2 w0 = *(const float2*)(Wold + i0);
                float2 w1 = *(const float2*)(Wold + i1);
                w0.x += scale * acc[mt][nt][0]; w0.y += scale * acc[mt][nt][1];
                w1.x += scale * acc[mt][nt][2]; w1.y += scale * acc[mt][nt][3];
                *(float2*)(C + i0) = w0;
                *(float2*)(C + i1) = w1;
            }
        }
    }

    // Fused column partial sums for threshold EMA (mode 0 only, deterministic)
    if (mode == 0) {
        float s0[8], s1[8];
        #pragma unroll
        for (int nt = 0; nt < 8; nt++) {
            float a0 = 0.f, a1 = 0.f;
            #pragma unroll
            for (int mt = 0; mt < 4; mt++) {
                a0 += acc[mt][nt][0] + acc[mt][nt][2];
                a1 += acc[mt][nt][1] + acc[mt][nt][3];
            }
            #pragma unroll
            for (int off = 4; off <= 16; off <<= 1) {
                a0 += __shfl_xor_sync(0xffffffffu, a0, off);
                a1 += __shfl_xor_sync(0xffffffffu, a1, off);
            }
            s0[nt] = a0; s1[nt] = a1;
        }
        float* csum = (float*)smem;           // 128 floats (stage bufs done)
        __syncthreads();
        if (wm == 1 && lr == 0) {
            #pragma unroll
            for (int nt = 0; nt < 8; nt++) {
                int col = wn * 64 + nt * 8 + lc * 2;
                csum[col] = s0[nt]; csum[col + 1] = s1[nt];
            }
        }
        __syncthreads();
        if (wm == 0 && lr == 0) {
            #pragma unroll
            for (int nt = 0; nt < 8; nt++) {
                int col = wn * 64 + nt * 8 + lc * 2;
                size_t gi = (size_t)blockIdx.y * N + nbase + col;
                g_partial[gi]     = s0[nt] + csum[col];
                g_partial[gi + 1] = s1[nt] + csum[col + 1];
            }
        }
    }
}

// ---------------------------------------------------------------------------
// Prep kernels
// ---------------------------------------------------------------------------
__global__ void h_kernel(const float* __restrict__ in, __half* __restrict__ out, size_t n4) {
    size_t i = (size_t)blockIdx.x * blockDim.x + threadIdx.x;
    if (i < n4) {
        float4 v = ((const float4*)in)[i];
        ((__half2*)out)[2 * i]     = __floats2half2_rn(v.x, v.y);
        ((__half2*)out)[2 * i + 1] = __floats2half2_rn(v.z, v.w);
    }
}

// One pass over x: XR[b][i] = rn(x[b][i]); XT[i][b] = rn(x[b][i])
__global__ void prep_x_kernel(const float* __restrict__ X, __half* __restrict__ XR,
                              __half* __restrict__ XT, int Bn, int INn) {
    __shared__ float t[32][33];
    int b0 = blockIdx.x * 32, i0 = blockIdx.y * 32;
    int tx = threadIdx.x, ty = threadIdx.y;
    for (int r = ty; r < 32; r += 8) {
        float v = X[(size_t)(b0 + r) * INn + i0 + tx];
        t[r][tx] = v;
        XR[(size_t)(b0 + r) * INn + i0 + tx] = __float2half_rn(v);
    }
    __syncthreads();
    for (int r = ty; r < 32; r += 8)
        XT[(size_t)(i0 + r) * Bn + b0 + tx] = __float2half_rn(t[tx][r]);
}

// PT[o][b] = rn(max(O[b][o] - th[o], 0))
__global__ void pt_kernel(const float* __restrict__ O, const float* __restrict__ th,
                          __half* __restrict__ PT, int Bn, int OUTn) {
    __shared__ float t[32][33];
    int b0 = blockIdx.x * 32, o0 = blockIdx.y * 32;
    int tx = threadIdx.x, ty = threadIdx.y;
    for (int r = ty; r < 32; r += 8)
        t[r][tx] = O[(size_t)(b0 + r) * OUTn + o0 + tx];
    __syncthreads();
    for (int r = ty; r < 32; r += 8) {
        float thv = __ldg(th + o0 + r);
        PT[(size_t)(o0 + r) * Bn + b0 + tx] = __float2half_rn(fmaxf(t[tx][r] - thv, 0.f));
    }
}

__global__ void thresh_kernel(const float* __restrict__ th_old,
                              float* __restrict__ th_new, int Bn, int OUTn) {
    int c = blockIdx.x * blockDim.x + threadIdx.x;
    if (c >= OUTn) return;
    float s = 0.f;
    #pragma unroll 8
    for (int p = 0; p < RSPLIT; p++) s += g_partial[p * OUTn + c];
    float act = s / (float)Bn;
    float t = th_old[c];
    th_new[c] = t + (act * act - t) / TAU_C;
}

// ---------------------------------------------------------------------------
extern "C" void kernel_launch(void* const* d_in, const int* in_sizes, int n_in,
                              void* d_out, int out_size)
{
    const float* x  = (const float*)d_in[0];
    const float* w  = (const float*)d_in[1];
    const float* th = (const float*)d_in[2];

    const int OUT = in_sizes[2];
    const int IN  = in_sizes[1] / OUT;
    const int Bn  = in_sizes[0] / IN;

    float* out    = (float*)d_out;
    float* out_O  = out;                          // B x OUT
    float* out_th = out + (size_t)Bn * OUT;       // OUT
    float* out_W  = out_th + OUT;                 // OUT x IN

    void *p;
    cudaGetSymbolAddress(&p, g_xr); __half* XR = (__half*)p;
    cudaGetSymbolAddress(&p, g_wr); __half* WR = (__half*)p;
    cudaGetSymbolAddress(&p, g_xt); __half* XT = (__half*)p;
    cudaGetSymbolAddress(&p, g_pt); __half* PT = (__half*)p;

    cudaFuncSetAttribute(gemm_mma_kernel,
                         cudaFuncAttributeMaxDynamicSharedMemorySize, SMEM_TOTAL);

    // Convert operands to fp16 (RN, unbiased; same 10-bit mantissa as tf32)
    size_t nW = (size_t)OUT * IN;
    prep_x_kernel<<<dim3(Bn / 32, IN / 32), dim3(32, 8)>>>(x, XR, XT, Bn, IN);
    h_kernel<<<(unsigned)((nW / 4 + 255) / 256), 256>>>(w, WR, nW / 4);

    // 1) O = X @ W^T   (M=B, N=OUT, K=IN), fused column partials
    dim3 g1(OUT / BN, Bn / BM);
    gemm_mma_kernel<<<g1, 128, SMEM_TOTAL>>>(XR, WR, nullptr, out_O,
                                             Bn, OUT, IN, 0.f, 0);

    // 2) threshold EMA (partials already produced by GEMM1)
    thresh_kernel<<<(OUT + 255) / 256, 256>>>(th, out_th, Bn, OUT);

    // 3) PT = relu(O - th)^T ; Wnew = W + (LR/B) * PT @ XT^T  (M=OUT, N=IN, K=B)
    pt_kernel<<<dim3(Bn / 32, OUT / 32), dim3(32, 8)>>>(out_O, out_th, PT, Bn, OUT);
    dim3 g2(IN / BN, OUT / BM);
    gemm_mma_kernel<<<g2, 128, SMEM_TOTAL>>>(PT, XT, w, out_W,
                                             OUT, IN, Bn, LR_C / (float)Bn, 1);
}

// round 12
// speedup vs baseline: 1.4589x; 1.4589x over previous
#include <cuda_runtime.h>
#include <cuda_fp16.h>
#include <cstdint>
#include <cstddef>

#define LR_C   0.001f
#define TAU_C  1000.0f

// GEMM tiling: 128x128 CTA tile, 4 warps (2x2), warp tile 64x64, fp16 BKT=64
#define BM 128
#define BN 128
#define BKT 64
#define NSTAGES 3
#define A_BYTES (BM * 128)                   // 16 KB (128 rows x 64 halves)
#define STAGE_BYTES (2 * A_BYTES)            // 32 KB
#define SMEM_TOTAL (NSTAGES * STAGE_BYTES)   // 96 KB -> 2 CTA/SM
#define RSPLIT 64                            // = DIM_B / BM

// Fixed problem shape: B=8192, IN=OUT=4096.
#define DIM_B   8192
#define DIM_IO  4096

// Scratch (__device__ globals: the sanctioned alloc-free workaround)
__device__ __half g_xr[(size_t)DIM_B * DIM_IO];   // rn(x)            B x IN
__device__ __half g_wr[(size_t)DIM_IO * DIM_IO];  // rn(w)            OUT x IN
__device__ __half g_xt[(size_t)DIM_IO * DIM_B];   // rn(x)^T          IN x B
__device__ __half g_pt[(size_t)DIM_IO * DIM_B];   // rn(relu(o-th))^T OUT x B
__device__ float  g_partial[RSPLIT * DIM_IO];

// ---------------------------------------------------------------------------
// PTX helpers (baseline sm_80+ features ONLY)
// ---------------------------------------------------------------------------
__device__ __forceinline__ uint32_t smem_u32(const void* p) {
    return (uint32_t)__cvta_generic_to_shared(p);
}

__device__ __forceinline__ void cp_async16(uint32_t s, const void* g) {
    asm volatile("cp.async.cg.shared.global [%0], [%1], 16;\n" :: "r"(s), "l"(g));
}
#define CP_COMMIT() asm volatile("cp.async.commit_group;\n" ::)
#define CP_WAIT1()  asm volatile("cp.async.wait_group 1;\n" ::: "memory")

__device__ __forceinline__ void ldsm_x4(uint32_t* r, uint32_t addr) {
    asm volatile("ldmatrix.sync.aligned.m8n8.x4.shared.b16 {%0,%1,%2,%3}, [%4];"
                 : "=r"(r[0]), "=r"(r[1]), "=r"(r[2]), "=r"(r[3]) : "r"(addr));
}

__device__ __forceinline__ uint32_t sw128(uint32_t off) {
    return off ^ ((off >> 3) & 0x70);
}

// m16n8k16 fp16 MMA, fp32 accumulate
__device__ __forceinline__ void mma_16816(float* c, const uint32_t* a,
                                          uint32_t b0, uint32_t b1) {
    asm volatile(
        "mma.sync.aligned.m16n8k16.row.col.f32.f16.f16.f32 "
        "{%0,%1,%2,%3}, {%4,%5,%6,%7}, {%8,%9}, {%0,%1,%2,%3};"
        : "+f"(c[0]), "+f"(c[1]), "+f"(c[2]), "+f"(c[3])
        : "r"(a[0]), "r"(a[1]), "r"(a[2]), "r"(a[3]), "r"(b0), "r"(b1));
}

// ---------------------------------------------------------------------------
// FP16 tensor-core GEMM: C[M,N] = A[M,K] * B[N,K]^T (both K-major half)
// mode 0: C = D, and fused per-CTA column sums -> g_partial[blockIdx.y][col]
// mode 1: C = Wold + scale * D
// SMEM layout: 128 rows x 128 bytes (64 halves = one BKT slice), SW128 swizzle.
// NOTE (R11 lesson): keep load_stage AFTER the ks-loop — issuing it early
// regressed 50% (LSU queue ahead of LDSM primes + register pressure).
// ---------------------------------------------------------------------------
__device__ __forceinline__ void load_stage(uint32_t smem_base, int stage,
                                           const __half* Ab, const __half* Bb,
                                           int K, int k0, int tid) {
    uint32_t sa = smem_base + stage * STAGE_BYTES;
    uint32_t sb = sa + A_BYTES;
    #pragma unroll
    for (int i = 0; i < 8; i++) {            // A: 128 rows x 8 x 16B chunks
        int idx = tid + i * 128;
        int row = idx >> 3, c = idx & 7;
        cp_async16(sa + sw128((uint32_t)(row * 128 + c * 16)),
                   (const char*)(Ab + (size_t)row * K + k0) + c * 16);
    }
    #pragma unroll
    for (int i = 0; i < 8; i++) {            // B: 128 rows x 8 x 16B chunks
        int idx = tid + i * 128;
        int row = idx >> 3, c = idx & 7;
        cp_async16(sb + sw128((uint32_t)(row * 128 + c * 16)),
                   (const char*)(Bb + (size_t)row * K + k0) + c * 16);
    }
}

__global__ __launch_bounds__(128, 2) void gemm_mma_kernel(
    const __half* __restrict__ A, const __half* __restrict__ Bmat,
    const float* __restrict__ Wold, float* __restrict__ C,
    int M, int N, int K, float scale, int mode)
{
    extern __shared__ char smem[];
    const uint32_t smem_base = smem_u32(smem);
    const int tid  = threadIdx.x;
    const int warp = tid >> 5, lane = tid & 31;
    const int wm = warp >> 1, wn = warp & 1;       // 2 x 2 warp grid, 64x64 each
    const int lr = lane >> 2, lc = lane & 3;

    const int mbase = blockIdx.y * BM;
    const int nbase = blockIdx.x * BN;
    const __half* Ab = A + (size_t)mbase * K;
    const __half* Bb = Bmat + (size_t)nbase * K;

    // ldmatrix addressing (128B smem rows, 16B chunks, swizzle mask (lane&7)<<4)
    const uint32_t swz_mask = (uint32_t)((lane & 7) << 4);
    const int arow = wm * 64 + ((lane >> 3) & 1) * 8 + (lane & 7);
    const uint32_t a_kb = (uint32_t)((lane >> 4) * 16);
    uint32_t a_rowoff[4];
    #pragma unroll
    for (int mt = 0; mt < 4; mt++) a_rowoff[mt] = (uint32_t)((arow + mt * 16) * 128);
    const int brow = wn * 64 + ((lane >> 4) & 1) * 8 + (lane & 7);
    const uint32_t b_kb = (uint32_t)(((lane >> 3) & 1) * 16);
    uint32_t b_rowoff[4];
    #pragma unroll
    for (int p = 0; p < 4; p++) b_rowoff[p] = (uint32_t)((brow + p * 16) * 128);

    float acc[4][8][4];                            // [mt][nt][frag]
    #pragma unroll
    for (int i = 0; i < 4; i++)
        #pragma unroll
        for (int j = 0; j < 8; j++)
            #pragma unroll
            for (int f = 0; f < 4; f++) acc[i][j][f] = 0.f;

    const int niter = K / BKT;

    load_stage(smem_base, 0, Ab, Bb, K, 0, tid);   CP_COMMIT();
    load_stage(smem_base, 1, Ab, Bb, K, BKT, tid); CP_COMMIT();

    // Fragment double buffer: load ks+1 while issuing MMAs of ks.
    uint32_t a[2][4][4], b[2][4][4];

    int buf = 0;
    for (int it = 0; it < niter; ++it) {
        CP_WAIT1();
        __syncthreads();
        uint32_t sa = smem_base + buf * STAGE_BYTES;
        uint32_t sb = sa + A_BYTES;

        // prime ks = 0
        {
            const uint32_t xa = a_kb ^ swz_mask;
            const uint32_t xb = b_kb ^ swz_mask;
            #pragma unroll
            for (int mt = 0; mt < 4; mt++) ldsm_x4(a[0][mt], sa + a_rowoff[mt] + xa);
            #pragma unroll
            for (int p = 0; p < 4; p++)    ldsm_x4(b[0][p], sb + b_rowoff[p] + xb);
        }

        #pragma unroll
        for (int ks = 0; ks < BKT / 16; ks++) {    // 4 k16-steps, 32B stride each
            const int cur = ks & 1, nxt = cur ^ 1;
            if (ks < BKT / 16 - 1) {               // prefetch next fragments
                const uint32_t xa = ((uint32_t)((ks + 1) * 32) + a_kb) ^ swz_mask;
                const uint32_t xb = ((uint32_t)((ks + 1) * 32) + b_kb) ^ swz_mask;
                #pragma unroll
                for (int mt = 0; mt < 4; mt++) ldsm_x4(a[nxt][mt], sa + a_rowoff[mt] + xa);
                #pragma unroll
                for (int p = 0; p < 4; p++)    ldsm_x4(b[nxt][p], sb + b_rowoff[p] + xb);
            }
            #pragma unroll
            for (int mt = 0; mt < 4; mt++) {
                #pragma unroll
                for (int p = 0; p < 4; p++) {
                    mma_16816(acc[mt][2 * p],     a[cur][mt], b[cur][p][0], b[cur][p][1]);
                    mma_16816(acc[mt][2 * p + 1], a[cur][mt], b[cur][p][2], b[cur][p][3]);
                }
            }
        }

        const int itn = it + 2;
        if (itn < niter)
            load_stage(smem_base, itn % NSTAGES, Ab, Bb, K, itn * BKT, tid);
        CP_COMMIT();
        buf = (buf + 1 == NSTAGES) ? 0 : buf + 1;
    }

    // Epilogue: per thread 4x8 tiles, two float2 rows each
    #pragma unroll
    for (int mt = 0; mt < 4; mt++) {
        int r0 = mbase + wm * 64 + mt * 16 + lr;
        #pragma unroll
        for (int nt = 0; nt < 8; nt++) {
            int cc = nbase + wn * 64 + nt * 8 + lc * 2;
            size_t i0 = (size_t)r0 * N + cc;
            size_t i1 = (size_t)(r0 + 8) * N + cc;
            if (mode == 0) {
                *(float2*)(C + i0) = make_float2(acc[mt][nt][0], acc[mt][nt][1]);
                *(float2*)(C + i1) = make_float2(acc[mt][nt][2], acc[mt][nt][3]);
            } else {
                float2 w0 = *(const float2*)(Wold + i0);
                float2 w1 = *(const float2*)(Wold + i1);
                w0.x += scale * acc[mt][nt][0]; w0.y += scale * acc[mt][nt][1];
                w1.x += scale * acc[mt][nt][2]; w1.y += scale * acc[mt][nt][3];
                *(float2*)(C + i0) = w0;
                *(float2*)(C + i1) = w1;
            }
        }
    }

    // Fused column partial sums for threshold EMA (mode 0 only, deterministic)
    if (mode == 0) {
        float s0[8], s1[8];
        #pragma unroll
        for (int nt = 0; nt < 8; nt++) {
            float a0 = 0.f, a1 = 0.f;
            #pragma unroll
            for (int mt = 0; mt < 4; mt++) {
                a0 += acc[mt][nt][0] + acc[mt][nt][2];
                a1 += acc[mt][nt][1] + acc[mt][nt][3];
            }
            #pragma unroll
            for (int off = 4; off <= 16; off <<= 1) {
                a0 += __shfl_xor_sync(0xffffffffu, a0, off);
                a1 += __shfl_xor_sync(0xffffffffu, a1, off);
            }
            s0[nt] = a0; s1[nt] = a1;
        }
        float* csum = (float*)smem;           // 128 floats (stage bufs done)
        __syncthreads();
        if (wm == 1 && lr == 0) {
            #pragma unroll
            for (int nt = 0; nt < 8; nt++) {
                int col = wn * 64 + nt * 8 + lc * 2;
                csum[col] = s0[nt]; csum[col + 1] = s1[nt];
            }
        }
        __syncthreads();
        if (wm == 0 && lr == 0) {
            #pragma unroll
            for (int nt = 0; nt < 8; nt++) {
                int col = wn * 64 + nt * 8 + lc * 2;
                size_t gi = (size_t)blockIdx.y * N + nbase + col;
                g_partial[gi]     = s0[nt] + csum[col];
                g_partial[gi + 1] = s1[nt] + csum[col + 1];
            }
        }
    }
}

// ---------------------------------------------------------------------------
// Prep kernels
// ---------------------------------------------------------------------------
__global__ void h_kernel(const float* __restrict__ in, __half* __restrict__ out, size_t n4) {
    size_t i = (size_t)blockIdx.x * blockDim.x + threadIdx.x;
    if (i < n4) {
        float4 v = ((const float4*)in)[i];
        ((__half2*)out)[2 * i]     = __floats2half2_rn(v.x, v.y);
        ((__half2*)out)[2 * i + 1] = __floats2half2_rn(v.z, v.w);
    }
}

// One pass over x: XR[b][i] = rn(x[b][i]); XT[i][b] = rn(x[b][i])
__global__ void prep_x_kernel(const float* __restrict__ X, __half* __restrict__ XR,
                              __half* __restrict__ XT, int Bn, int INn) {
    __shared__ float t[32][33];
    int b0 = blockIdx.x * 32, i0 = blockIdx.y * 32;
    int tx = threadIdx.x, ty = threadIdx.y;
    for (int r = ty; r < 32; r += 8) {
        float v = X[(size_t)(b0 + r) * INn + i0 + tx];
        t[r][tx] = v;
        XR[(size_t)(b0 + r) * INn + i0 + tx] = __float2half_rn(v);
    }
    __syncthreads();
    for (int r = ty; r < 32; r += 8)
        XT[(size_t)(i0 + r) * Bn + b0 + tx] = __float2half_rn(t[tx][r]);
}

// Fused threshold EMA + PT build. Grid: (4 b-quarters, OUT/32). Block (32,8).
// Each block computes th_new for its 32 columns from g_partial (deterministic,
// identical order in every block), bx==0 writes out_th; then streams its
// quarter of the relu-transpose: PT[o][b] = rn(max(O[b][o] - th_new[o], 0)).
__global__ void ptth_kernel(const float* __restrict__ O, const float* __restrict__ th_old,
                            float* __restrict__ th_new_out, __half* __restrict__ PT,
                            int Bn, int OUTn) {
    __shared__ float red[8][32];
    __shared__ float ths[32];
    __shared__ float t[32][33];
    const int tx = threadIdx.x, ty = threadIdx.y;
    const int o0 = blockIdx.y * 32;

    // 1) threshold for columns o0..o0+31
    float s = 0.f;
    #pragma unroll
    for (int p = ty; p < RSPLIT; p += 8)
        s += g_partial[(size_t)p * OUTn + o0 + tx];
    red[ty][tx] = s;
    __syncthreads();
    if (ty == 0) {
        float tot = 0.f;
        #pragma unroll
        for (int q = 0; q < 8; q++) tot += red[q][tx];
        float act = tot / (float)Bn;
        float tv = th_old[o0 + tx];
        float thn = tv + (act * act - tv) / TAU_C;
        ths[tx] = thn;
        if (blockIdx.x == 0) th_new_out[o0 + tx] = thn;
    }
    __syncthreads();

    // 2) relu-transpose this block's quarter of the batch
    const int nbt = (Bn / 32) / 4;                 // 64 b-tiles per block
    for (int bt = 0; bt < nbt; bt++) {
        int b0 = (blockIdx.x * nbt + bt) * 32;
        #pragma unroll
        for (int r = ty; r < 32; r += 8)
            t[r][tx] = O[(size_t)(b0 + r) * OUTn + o0 + tx];
        __syncthreads();
        #pragma unroll
        for (int r = ty; r < 32; r += 8)
            PT[(size_t)(o0 + r) * Bn + b0 + tx] =
                __float2half_rn(fmaxf(t[tx][r] - ths[r], 0.f));
        __syncthreads();
    }
}

// ---------------------------------------------------------------------------
extern "C" void kernel_launch(void* const* d_in, const int* in_sizes, int n_in,
                              void* d_out, int out_size)
{
    const float* x  = (const float*)d_in[0];
    const float* w  = (const float*)d_in[1];
    const float* th = (const float*)d_in[2];

    const int OUT = in_sizes[2];
    const int IN  = in_sizes[1] / OUT;
    const int Bn  = in_sizes[0] / IN;

    float* out    = (float*)d_out;
    float* out_O  = out;                          // B x OUT
    float* out_th = out + (size_t)Bn * OUT;       // OUT
    float* out_W  = out_th + OUT;                 // OUT x IN

    void *p;
    cudaGetSymbolAddress(&p, g_xr); __half* XR = (__half*)p;
    cudaGetSymbolAddress(&p, g_wr); __half* WR = (__half*)p;
    cudaGetSymbolAddress(&p, g_xt); __half* XT = (__half*)p;
    cudaGetSymbolAddress(&p, g_pt); __half* PT = (__half*)p;

    cudaFuncSetAttribute(gemm_mma_kernel,
                         cudaFuncAttributeMaxDynamicSharedMemorySize, SMEM_TOTAL);

    // Convert operands to fp16 (RN, unbiased; same 10-bit mantissa as tf32)
    size_t nW = (size_t)OUT * IN;
    prep_x_kernel<<<dim3(Bn / 32, IN / 32), dim3(32, 8)>>>(x, XR, XT, Bn, IN);
    h_kernel<<<(unsigned)((nW / 4 + 255) / 256), 256>>>(w, WR, nW / 4);

    // 1) O = X @ W^T   (M=B, N=OUT, K=IN), fused column partials
    dim3 g1(OUT / BN, Bn / BM);
    gemm_mma_kernel<<<g1, 128, SMEM_TOTAL>>>(XR, WR, nullptr, out_O,
                                             Bn, OUT, IN, 0.f, 0);

    // 2+3a) fused threshold EMA + PT = relu(O - th)^T
    ptth_kernel<<<dim3(4, OUT / 32), dim3(32, 8)>>>(out_O, th, out_th, PT, Bn, OUT);

    // 3b) Wnew = W + (LR/B) * PT @ XT^T  (M=OUT, N=IN, K=B)
    dim3 g2(IN / BN, OUT / BM);
    gemm_mma_kernel<<<g2, 128, SMEM_TOTAL>>>(PT, XT, w, out_W,
                                             OUT, IN, Bn, LR_C / (float)Bn, 1);
}

// round 13
// speedup vs baseline: 1.5456x; 1.0594x over previous
#include <cuda_runtime.h>
#include <cuda_fp16.h>
#include <cstdint>
#include <cstddef>

#define LR_C   0.001f
#define TAU_C  1000.0f

// GEMM tiling: 128x128 CTA tile, 4 warps (2x2), warp tile 64x64, fp16 BKT=64
#define BM 128
#define BN 128
#define BKT 64
#define NSTAGES 3
#define A_BYTES (BM * 128)                   // 16 KB (128 rows x 64 halves)
#define STAGE_BYTES (2 * A_BYTES)            // 32 KB
#define SMEM_TOTAL (NSTAGES * STAGE_BYTES)   // 96 KB -> 2 CTA/SM
#define RSPLIT 64                            // = DIM_B / BM

// Fixed problem shape: B=8192, IN=OUT=4096.
#define DIM_B   8192
#define DIM_IO  4096

// Scratch (__device__ globals: the sanctioned alloc-free workaround)
__device__ __half g_xr[(size_t)DIM_B * DIM_IO];   // rn(x)            B x IN
__device__ __half g_wr[(size_t)DIM_IO * DIM_IO];  // rn(w)            OUT x IN
__device__ __half g_xt[(size_t)DIM_IO * DIM_B];   // rn(x)^T          IN x B
__device__ __half g_pt[(size_t)DIM_IO * DIM_B];   // rn(relu(o-th))^T OUT x B
__device__ float  g_partial[RSPLIT * DIM_IO];

// ---------------------------------------------------------------------------
// PTX helpers (baseline sm_80+ features ONLY)
// ---------------------------------------------------------------------------
__device__ __forceinline__ uint32_t smem_u32(const void* p) {
    return (uint32_t)__cvta_generic_to_shared(p);
}

__device__ __forceinline__ void cp_async16(uint32_t s, const void* g) {
    asm volatile("cp.async.cg.shared.global [%0], [%1], 16;\n" :: "r"(s), "l"(g));
}
#define CP_COMMIT() asm volatile("cp.async.commit_group;\n" ::)
#define CP_WAIT1()  asm volatile("cp.async.wait_group 1;\n" ::: "memory")

__device__ __forceinline__ void ldsm_x4(uint32_t* r, uint32_t addr) {
    asm volatile("ldmatrix.sync.aligned.m8n8.x4.shared.b16 {%0,%1,%2,%3}, [%4];"
                 : "=r"(r[0]), "=r"(r[1]), "=r"(r[2]), "=r"(r[3]) : "r"(addr));
}

__device__ __forceinline__ uint32_t sw128(uint32_t off) {
    return off ^ ((off >> 3) & 0x70);
}

// m16n8k16 fp16 MMA, fp32 accumulate
__device__ __forceinline__ void mma_16816(float* c, const uint32_t* a,
                                          uint32_t b0, uint32_t b1) {
    asm volatile(
        "mma.sync.aligned.m16n8k16.row.col.f32.f16.f16.f32 "
        "{%0,%1,%2,%3}, {%4,%5,%6,%7}, {%8,%9}, {%0,%1,%2,%3};"
        : "+f"(c[0]), "+f"(c[1]), "+f"(c[2]), "+f"(c[3])
        : "r"(a[0]), "r"(a[1]), "r"(a[2]), "r"(a[3]), "r"(b0), "r"(b1));
}

// ---------------------------------------------------------------------------
// FP16 tensor-core GEMM: C[M,N] = A[M,K] * B[N,K]^T (both K-major half)
// mode 0: C = D, and fused per-CTA column sums -> g_partial[blockIdx.y][col]
// mode 1: C = Wold + scale * D
// SMEM layout: 128 rows x 128 bytes (64 halves = one BKT slice), SW128 swizzle.
// NOTE (R11 lesson): keep load_stage AFTER the ks-loop — issuing it early
// regressed 50% (LSU queue ahead of LDSM primes + register pressure).
// ---------------------------------------------------------------------------
__device__ __forceinline__ void load_stage(uint32_t smem_base, int stage,
                                           const __half* Ab, const __half* Bb,
                                           int K, int k0, int tid) {
    uint32_t sa = smem_base + stage * STAGE_BYTES;
    uint32_t sb = sa + A_BYTES;
    #pragma unroll
    for (int i = 0; i < 8; i++) {            // A: 128 rows x 8 x 16B chunks
        int idx = tid + i * 128;
        int row = idx >> 3, c = idx & 7;
        cp_async16(sa + sw128((uint32_t)(row * 128 + c * 16)),
                   (const char*)(Ab + (size_t)row * K + k0) + c * 16);
    }
    #pragma unroll
    for (int i = 0; i < 8; i++) {            // B: 128 rows x 8 x 16B chunks
        int idx = tid + i * 128;
        int row = idx >> 3, c = idx & 7;
        cp_async16(sb + sw128((uint32_t)(row * 128 + c * 16)),
                   (const char*)(Bb + (size_t)row * K + k0) + c * 16);
    }
}

__global__ __launch_bounds__(128, 2) void gemm_mma_kernel(
    const __half* __restrict__ A, const __half* __restrict__ Bmat,
    const float* __restrict__ Wold, float* __restrict__ C,
    int M, int N, int K, float scale, int mode)
{
    extern __shared__ char smem[];
    const uint32_t smem_base = smem_u32(smem);
    const int tid  = threadIdx.x;
    const int warp = tid >> 5, lane = tid & 31;
    const int wm = warp >> 1, wn = warp & 1;       // 2 x 2 warp grid, 64x64 each
    const int lr = lane >> 2, lc = lane & 3;

    const int mbase = blockIdx.y * BM;
    const int nbase = blockIdx.x * BN;
    const __half* Ab = A + (size_t)mbase * K;
    const __half* Bb = Bmat + (size_t)nbase * K;

    // ldmatrix addressing (128B smem rows, 16B chunks, swizzle mask (lane&7)<<4)
    const uint32_t swz_mask = (uint32_t)((lane & 7) << 4);
    const int arow = wm * 64 + ((lane >> 3) & 1) * 8 + (lane & 7);
    const uint32_t a_kb = (uint32_t)((lane >> 4) * 16);
    uint32_t a_rowoff[4];
    #pragma unroll
    for (int mt = 0; mt < 4; mt++) a_rowoff[mt] = (uint32_t)((arow + mt * 16) * 128);
    const int brow = wn * 64 + ((lane >> 4) & 1) * 8 + (lane & 7);
    const uint32_t b_kb = (uint32_t)(((lane >> 3) & 1) * 16);
    uint32_t b_rowoff[4];
    #pragma unroll
    for (int p = 0; p < 4; p++) b_rowoff[p] = (uint32_t)((brow + p * 16) * 128);

    float acc[4][8][4];                            // [mt][nt][frag]
    #pragma unroll
    for (int i = 0; i < 4; i++)
        #pragma unroll
        for (int j = 0; j < 8; j++)
            #pragma unroll
            for (int f = 0; f < 4; f++) acc[i][j][f] = 0.f;

    const int niter = K / BKT;

    load_stage(smem_base, 0, Ab, Bb, K, 0, tid);   CP_COMMIT();
    load_stage(smem_base, 1, Ab, Bb, K, BKT, tid); CP_COMMIT();

    // Fragment double buffer: load ks+1 while issuing MMAs of ks.
    uint32_t a[2][4][4], b[2][4][4];

    int buf = 0;
    for (int it = 0; it < niter; ++it) {
        CP_WAIT1();
        __syncthreads();
        uint32_t sa = smem_base + buf * STAGE_BYTES;
        uint32_t sb = sa + A_BYTES;

        // prime ks = 0
        {
            const uint32_t xa = a_kb ^ swz_mask;
            const uint32_t xb = b_kb ^ swz_mask;
            #pragma unroll
            for (int mt = 0; mt < 4; mt++) ldsm_x4(a[0][mt], sa + a_rowoff[mt] + xa);
            #pragma unroll
            for (int p = 0; p < 4; p++)    ldsm_x4(b[0][p], sb + b_rowoff[p] + xb);
        }

        #pragma unroll
        for (int ks = 0; ks < BKT / 16; ks++) {    // 4 k16-steps, 32B stride each
            const int cur = ks & 1, nxt = cur ^ 1;
            if (ks < BKT / 16 - 1) {               // prefetch next fragments
                const uint32_t xa = ((uint32_t)((ks + 1) * 32) + a_kb) ^ swz_mask;
                const uint32_t xb = ((uint32_t)((ks + 1) * 32) + b_kb) ^ swz_mask;
                #pragma unroll
                for (int mt = 0; mt < 4; mt++) ldsm_x4(a[nxt][mt], sa + a_rowoff[mt] + xa);
                #pragma unroll
                for (int p = 0; p < 4; p++)    ldsm_x4(b[nxt][p], sb + b_rowoff[p] + xb);
            }
            #pragma unroll
            for (int mt = 0; mt < 4; mt++) {
                #pragma unroll
                for (int p = 0; p < 4; p++) {
                    mma_16816(acc[mt][2 * p],     a[cur][mt], b[cur][p][0], b[cur][p][1]);
                    mma_16816(acc[mt][2 * p + 1], a[cur][mt], b[cur][p][2], b[cur][p][3]);
                }
            }
        }

        const int itn = it + 2;
        if (itn < niter)
            load_stage(smem_base, itn % NSTAGES, Ab, Bb, K, itn * BKT, tid);
        CP_COMMIT();
        buf = (buf + 1 == NSTAGES) ? 0 : buf + 1;
    }

    // Epilogue: per thread 4x8 tiles, two float2 rows each
    #pragma unroll
    for (int mt = 0; mt < 4; mt++) {
        int r0 = mbase + wm * 64 + mt * 16 + lr;
        #pragma unroll
        for (int nt = 0; nt < 8; nt++) {
            int cc = nbase + wn * 64 + nt * 8 + lc * 2;
            size_t i0 = (size_t)r0 * N + cc;
            size_t i1 = (size_t)(r0 + 8) * N + cc;
            if (mode == 0) {
                *(float2*)(C + i0) = make_float2(acc[mt][nt][0], acc[mt][nt][1]);
                *(float2*)(C + i1) = make_float2(acc[mt][nt][2], acc[mt][nt][3]);
            } else {
                float2 w0 = *(const float2*)(Wold + i0);
                float2 w1 = *(const float2*)(Wold + i1);
                w0.x += scale * acc[mt][nt][0]; w0.y += scale * acc[mt][nt][1];
                w1.x += scale * acc[mt][nt][2]; w1.y += scale * acc[mt][nt][3];
                *(float2*)(C + i0) = w0;
                *(float2*)(C + i1) = w1;
            }
        }
    }

    // Fused column partial sums for threshold EMA (mode 0 only, deterministic)
    if (mode == 0) {
        float s0[8], s1[8];
        #pragma unroll
        for (int nt = 0; nt < 8; nt++) {
            float a0 = 0.f, a1 = 0.f;
            #pragma unroll
            for (int mt = 0; mt < 4; mt++) {
                a0 += acc[mt][nt][0] + acc[mt][nt][2];
                a1 += acc[mt][nt][1] + acc[mt][nt][3];
            }
            #pragma unroll
            for (int off = 4; off <= 16; off <<= 1) {
                a0 += __shfl_xor_sync(0xffffffffu, a0, off);
                a1 += __shfl_xor_sync(0xffffffffu, a1, off);
            }
            s0[nt] = a0; s1[nt] = a1;
        }
        float* csum = (float*)smem;           // 128 floats (stage bufs done)
        __syncthreads();
        if (wm == 1 && lr == 0) {
            #pragma unroll
            for (int nt = 0; nt < 8; nt++) {
                int col = wn * 64 + nt * 8 + lc * 2;
                csum[col] = s0[nt]; csum[col + 1] = s1[nt];
            }
        }
        __syncthreads();
        if (wm == 0 && lr == 0) {
            #pragma unroll
            for (int nt = 0; nt < 8; nt++) {
                int col = wn * 64 + nt * 8 + lc * 2;
                size_t gi = (size_t)blockIdx.y * N + nbase + col;
                g_partial[gi]     = s0[nt] + csum[col];
                g_partial[gi + 1] = s1[nt] + csum[col + 1];
            }
        }
    }
}

// ---------------------------------------------------------------------------
// Prep kernels
// ---------------------------------------------------------------------------
__global__ void h_kernel(const float* __restrict__ in, __half* __restrict__ out, size_t n4) {
    size_t i = (size_t)blockIdx.x * blockDim.x + threadIdx.x;
    if (i < n4) {
        float4 v = ((const float4*)in)[i];
        ((__half2*)out)[2 * i]     = __floats2half2_rn(v.x, v.y);
        ((__half2*)out)[2 * i + 1] = __floats2half2_rn(v.z, v.w);
    }
}

// One pass over x: XR[b][i] = rn(x[b][i]); XT[i][b] = rn(x[b][i])
__global__ void prep_x_kernel(const float* __restrict__ X, __half* __restrict__ XR,
                              __half* __restrict__ XT, int Bn, int INn) {
    __shared__ float t[32][33];
    int b0 = blockIdx.x * 32, i0 = blockIdx.y * 32;
    int tx = threadIdx.x, ty = threadIdx.y;
    for (int r = ty; r < 32; r += 8) {
        float v = X[(size_t)(b0 + r) * INn + i0 + tx];
        t[r][tx] = v;
        XR[(size_t)(b0 + r) * INn + i0 + tx] = __float2half_rn(v);
    }
    __syncthreads();
    for (int r = ty; r < 32; r += 8)
        XT[(size_t)(i0 + r) * Bn + b0 + tx] = __float2half_rn(t[tx][r]);
}

// PT[o][b] = rn(max(O[b][o] - th[o], 0)); 64x64 tiles, float2 in / half2 out.
__global__ void pt_kernel(const float* __restrict__ O, const float* __restrict__ th,
                          __half* __restrict__ PT, int Bn, int OUTn) {
    __shared__ float t[64][65];
    __shared__ float ths[64];
    const int b0 = blockIdx.x * 64, o0 = blockIdx.y * 64;
    const int tx = threadIdx.x, ty = threadIdx.y;   // 32 x 8
    const int tid = ty * 32 + tx;
    if (tid < 64) ths[tid] = th[o0 + tid];
    #pragma unroll
    for (int r = ty; r < 64; r += 8) {
        float2 v = *(const float2*)(O + (size_t)(b0 + r) * OUTn + o0 + 2 * tx);
        t[r][2 * tx] = v.x; t[r][2 * tx + 1] = v.y;
    }
    __syncthreads();
    #pragma unroll
    for (int r = ty; r < 64; r += 8) {
        float thv = ths[r];
        __half2 h = __floats2half2_rn(fmaxf(t[2 * tx][r] - thv, 0.f),
                                      fmaxf(t[2 * tx + 1][r] - thv, 0.f));
        *(__half2*)(PT + (size_t)(o0 + r) * Bn + b0 + 2 * tx) = h;
    }
}

__global__ void thresh_kernel(const float* __restrict__ th_old,
                              float* __restrict__ th_new, int Bn, int OUTn) {
    int c = blockIdx.x * blockDim.x + threadIdx.x;
    if (c >= OUTn) return;
    float s = 0.f;
    #pragma unroll 8
    for (int p = 0; p < RSPLIT; p++) s += g_partial[p * OUTn + c];
    float act = s / (float)Bn;
    float t = th_old[c];
    th_new[c] = t + (act * act - t) / TAU_C;
}

// ---------------------------------------------------------------------------
extern "C" void kernel_launch(void* const* d_in, const int* in_sizes, int n_in,
                              void* d_out, int out_size)
{
    const float* x  = (const float*)d_in[0];
    const float* w  = (const float*)d_in[1];
    const float* th = (const float*)d_in[2];

    const int OUT = in_sizes[2];
    const int IN  = in_sizes[1] / OUT;
    const int Bn  = in_sizes[0] / IN;

    float* out    = (float*)d_out;
    float* out_O  = out;                          // B x OUT
    float* out_th = out + (size_t)Bn * OUT;       // OUT
    float* out_W  = out_th + OUT;                 // OUT x IN

    void *p;
    cudaGetSymbolAddress(&p, g_xr); __half* XR = (__half*)p;
    cudaGetSymbolAddress(&p, g_wr); __half* WR = (__half*)p;
    cudaGetSymbolAddress(&p, g_xt); __half* XT = (__half*)p;
    cudaGetSymbolAddress(&p, g_pt); __half* PT = (__half*)p;

    cudaFuncSetAttribute(gemm_mma_kernel,
                         cudaFuncAttributeMaxDynamicSharedMemorySize, SMEM_TOTAL);

    // Convert operands to fp16 (RN, unbiased; same 10-bit mantissa as tf32)
    size_t nW = (size_t)OUT * IN;
    prep_x_kernel<<<dim3(Bn / 32, IN / 32), dim3(32, 8)>>>(x, XR, XT, Bn, IN);
    h_kernel<<<(unsigned)((nW / 4 + 255) / 256), 256>>>(w, WR, nW / 4);

    // 1) O = X @ W^T   (M=B, N=OUT, K=IN), fused column partials
    dim3 g1(OUT / BN, Bn / BM);
    gemm_mma_kernel<<<g1, 128, SMEM_TOTAL>>>(XR, WR, nullptr, out_O,
                                             Bn, OUT, IN, 0.f, 0);

    // 2) threshold EMA (partials already produced by GEMM1)
    thresh_kernel<<<(OUT + 255) / 256, 256>>>(th, out_th, Bn, OUT);

    // 3) PT = relu(O - th)^T ; Wnew = W + (LR/B) * PT @ XT^T  (M=OUT, N=IN, K=B)
    pt_kernel<<<dim3(Bn / 64, OUT / 64), dim3(32, 8)>>>(out_O, out_th, PT, Bn, OUT);
    dim3 g2(IN / BN, OUT / BM);
    gemm_mma_kernel<<<g2, 128, SMEM_TOTAL>>>(PT, XT, w, out_W,
                                             OUT, IN, Bn, LR_C / (float)Bn, 1);
}

// round 14
// speedup vs baseline: 1.5828x; 1.0241x over previous
#include <cuda_runtime.h>
#include <cuda_fp16.h>
#include <cstdint>
#include <cstddef>

#define LR_C   0.001f
#define TAU_C  1000.0f

// GEMM tiling: 128x128 CTA tile, 4 warps (2x2), warp tile 64x64, fp16 BKT=64
#define BM 128
#define BN 128
#define BKT 64
#define NSTAGES 3
#define A_BYTES (BM * 128)                   // 16 KB (128 rows x 64 halves)
#define STAGE_BYTES (2 * A_BYTES)            // 32 KB
#define SMEM_TOTAL (NSTAGES * STAGE_BYTES)   // 96 KB -> 2 CTA/SM
#define RSPLIT 64                            // = DIM_B / BM

// Fixed problem shape: B=8192, IN=OUT=4096.
#define DIM_B   8192
#define DIM_IO  4096

// Scratch (__device__ globals: the sanctioned alloc-free workaround)
__device__ __half g_xr[(size_t)DIM_B * DIM_IO];   // rn(x)            B x IN
__device__ __half g_wr[(size_t)DIM_IO * DIM_IO];  // rn(w)            OUT x IN
__device__ __half g_xt[(size_t)DIM_IO * DIM_B];   // rn(x)^T          IN x B
__device__ __half g_pt[(size_t)DIM_IO * DIM_B];   // rn(relu(o-th))^T OUT x B
__device__ float  g_partial[RSPLIT * DIM_IO];

// ---------------------------------------------------------------------------
// PTX helpers (baseline sm_80+ features ONLY)
// ---------------------------------------------------------------------------
__device__ __forceinline__ uint32_t smem_u32(const void* p) {
    return (uint32_t)__cvta_generic_to_shared(p);
}

__device__ __forceinline__ void cp_async16(uint32_t s, const void* g) {
    asm volatile("cp.async.cg.shared.global [%0], [%1], 16;\n" :: "r"(s), "l"(g));
}
#define CP_COMMIT() asm volatile("cp.async.commit_group;\n" ::)
#define CP_WAIT1()  asm volatile("cp.async.wait_group 1;\n" ::: "memory")

__device__ __forceinline__ void ldsm_x4(uint32_t* r, uint32_t addr) {
    asm volatile("ldmatrix.sync.aligned.m8n8.x4.shared.b16 {%0,%1,%2,%3}, [%4];"
                 : "=r"(r[0]), "=r"(r[1]), "=r"(r[2]), "=r"(r[3]) : "r"(addr));
}

__device__ __forceinline__ uint32_t sw128(uint32_t off) {
    return off ^ ((off >> 3) & 0x70);
}

// m16n8k16 fp16 MMA, fp32 accumulate
__device__ __forceinline__ void mma_16816(float* c, const uint32_t* a,
                                          uint32_t b0, uint32_t b1) {
    asm volatile(
        "mma.sync.aligned.m16n8k16.row.col.f32.f16.f16.f32 "
        "{%0,%1,%2,%3}, {%4,%5,%6,%7}, {%8,%9}, {%0,%1,%2,%3};"
        : "+f"(c[0]), "+f"(c[1]), "+f"(c[2]), "+f"(c[3])
        : "r"(a[0]), "r"(a[1]), "r"(a[2]), "r"(a[3]), "r"(b0), "r"(b1));
}

// ---------------------------------------------------------------------------
// FP16 tensor-core GEMM: C[M,N] = A[M,K] * B[N,K]^T (both K-major half)
// mode 0: C = D, and fused per-CTA column sums -> g_partial[blockIdx.y][col]
// mode 1: C = Wold + scale * D
// SMEM layout: 128 rows x 128 bytes (64 halves = one BKT slice), SW128 swizzle.
// NOTE (R11 lesson): keep load_stage AFTER the ks-loop — issuing it early
// regressed 50% (LSU queue ahead of LDSM primes + register pressure).
// ---------------------------------------------------------------------------
__device__ __forceinline__ void load_stage(uint32_t smem_base, int stage,
                                           const __half* Ab, const __half* Bb,
                                           int K, int k0, int tid) {
    uint32_t sa = smem_base + stage * STAGE_BYTES;
    uint32_t sb = sa + A_BYTES;
    #pragma unroll
    for (int i = 0; i < 8; i++) {            // A: 128 rows x 8 x 16B chunks
        int idx = tid + i * 128;
        int row = idx >> 3, c = idx & 7;
        cp_async16(sa + sw128((uint32_t)(row * 128 + c * 16)),
                   (const char*)(Ab + (size_t)row * K + k0) + c * 16);
    }
    #pragma unroll
    for (int i = 0; i < 8; i++) {            // B: 128 rows x 8 x 16B chunks
        int idx = tid + i * 128;
        int row = idx >> 3, c = idx & 7;
        cp_async16(sb + sw128((uint32_t)(row * 128 + c * 16)),
                   (const char*)(Bb + (size_t)row * K + k0) + c * 16);
    }
}

__global__ __launch_bounds__(128, 2) void gemm_mma_kernel(
    const __half* __restrict__ A, const __half* __restrict__ Bmat,
    const float* __restrict__ Wold, float* __restrict__ C,
    int M, int N, int K, float scale, int mode)
{
    extern __shared__ char smem[];
    const uint32_t smem_base = smem_u32(smem);
    const int tid  = threadIdx.x;
    const int warp = tid >> 5, lane = tid & 31;
    const int wm = warp >> 1, wn = warp & 1;       // 2 x 2 warp grid, 64x64 each
    const int lr = lane >> 2, lc = lane & 3;

    const int mbase = blockIdx.y * BM;
    const int nbase = blockIdx.x * BN;
    const __half* Ab = A + (size_t)mbase * K;
    const __half* Bb = Bmat + (size_t)nbase * K;

    // ldmatrix addressing (128B smem rows, 16B chunks, swizzle mask (lane&7)<<4)
    const uint32_t swz_mask = (uint32_t)((lane & 7) << 4);
    const int arow = wm * 64 + ((lane >> 3) & 1) * 8 + (lane & 7);
    const uint32_t a_kb = (uint32_t)((lane >> 4) * 16);
    uint32_t a_rowoff[4];
    #pragma unroll
    for (int mt = 0; mt < 4; mt++) a_rowoff[mt] = (uint32_t)((arow + mt * 16) * 128);
    const int brow = wn * 64 + ((lane >> 4) & 1) * 8 + (lane & 7);
    const uint32_t b_kb = (uint32_t)(((lane >> 3) & 1) * 16);
    uint32_t b_rowoff[4];
    #pragma unroll
    for (int p = 0; p < 4; p++) b_rowoff[p] = (uint32_t)((brow + p * 16) * 128);

    float acc[4][8][4];                            // [mt][nt][frag]
    #pragma unroll
    for (int i = 0; i < 4; i++)
        #pragma unroll
        for (int j = 0; j < 8; j++)
            #pragma unroll
            for (int f = 0; f < 4; f++) acc[i][j][f] = 0.f;

    const int niter = K / BKT;

    load_stage(smem_base, 0, Ab, Bb, K, 0, tid);   CP_COMMIT();
    load_stage(smem_base, 1, Ab, Bb, K, BKT, tid); CP_COMMIT();

    // Fragment double buffer: load ks+1 while issuing MMAs of ks.
    uint32_t a[2][4][4], b[2][4][4];

    int buf = 0;
    for (int it = 0; it < niter; ++it) {
        CP_WAIT1();
        __syncthreads();
        uint32_t sa = smem_base + buf * STAGE_BYTES;
        uint32_t sb = sa + A_BYTES;

        // prime ks = 0
        {
            const uint32_t xa = a_kb ^ swz_mask;
            const uint32_t xb = b_kb ^ swz_mask;
            #pragma unroll
            for (int mt = 0; mt < 4; mt++) ldsm_x4(a[0][mt], sa + a_rowoff[mt] + xa);
            #pragma unroll
            for (int p = 0; p < 4; p++)    ldsm_x4(b[0][p], sb + b_rowoff[p] + xb);
        }

        #pragma unroll
        for (int ks = 0; ks < BKT / 16; ks++) {    // 4 k16-steps, 32B stride each
            const int cur = ks & 1, nxt = cur ^ 1;
            if (ks < BKT / 16 - 1) {               // prefetch next fragments
                const uint32_t xa = ((uint32_t)((ks + 1) * 32) + a_kb) ^ swz_mask;
                const uint32_t xb = ((uint32_t)((ks + 1) * 32) + b_kb) ^ swz_mask;
                #pragma unroll
                for (int mt = 0; mt < 4; mt++) ldsm_x4(a[nxt][mt], sa + a_rowoff[mt] + xa);
                #pragma unroll
                for (int p = 0; p < 4; p++)    ldsm_x4(b[nxt][p], sb + b_rowoff[p] + xb);
            }
            #pragma unroll
            for (int mt = 0; mt < 4; mt++) {
                #pragma unroll
                for (int p = 0; p < 4; p++) {
                    mma_16816(acc[mt][2 * p],     a[cur][mt], b[cur][p][0], b[cur][p][1]);
                    mma_16816(acc[mt][2 * p + 1], a[cur][mt], b[cur][p][2], b[cur][p][3]);
                }
            }
        }

        const int itn = it + 2;
        if (itn < niter)
            load_stage(smem_base, itn % NSTAGES, Ab, Bb, K, itn * BKT, tid);
        CP_COMMIT();
        buf = (buf + 1 == NSTAGES) ? 0 : buf + 1;
    }

    // Epilogue: per thread 4x8 tiles, two float2 rows each
    #pragma unroll
    for (int mt = 0; mt < 4; mt++) {
        int r0 = mbase + wm * 64 + mt * 16 + lr;
        #pragma unroll
        for (int nt = 0; nt < 8; nt++) {
            int cc = nbase + wn * 64 + nt * 8 + lc * 2;
            size_t i0 = (size_t)r0 * N + cc;
            size_t i1 = (size_t)(r0 + 8) * N + cc;
            if (mode == 0) {
                *(float2*)(C + i0) = make_float2(acc[mt][nt][0], acc[mt][nt][1]);
                *(float2*)(C + i1) = make_float2(acc[mt][nt][2], acc[mt][nt][3]);
            } else {
                float2 w0 = *(const float2*)(Wold + i0);
                float2 w1 = *(const float2*)(Wold + i1);
                w0.x += scale * acc[mt][nt][0]; w0.y += scale * acc[mt][nt][1];
                w1.x += scale * acc[mt][nt][2]; w1.y += scale * acc[mt][nt][3];
                *(float2*)(C + i0) = w0;
                *(float2*)(C + i1) = w1;
            }
        }
    }

    // Fused column partial sums for threshold EMA (mode 0 only, deterministic)
    if (mode == 0) {
        float s0[8], s1[8];
        #pragma unroll
        for (int nt = 0; nt < 8; nt++) {
            float a0 = 0.f, a1 = 0.f;
            #pragma unroll
            for (int mt = 0; mt < 4; mt++) {
                a0 += acc[mt][nt][0] + acc[mt][nt][2];
                a1 += acc[mt][nt][1] + acc[mt][nt][3];
            }
            #pragma unroll
            for (int off = 4; off <= 16; off <<= 1) {
                a0 += __shfl_xor_sync(0xffffffffu, a0, off);
                a1 += __shfl_xor_sync(0xffffffffu, a1, off);
            }
            s0[nt] = a0; s1[nt] = a1;
        }
        float* csum = (float*)smem;           // 128 floats (stage bufs done)
        __syncthreads();
        if (wm == 1 && lr == 0) {
            #pragma unroll
            for (int nt = 0; nt < 8; nt++) {
                int col = wn * 64 + nt * 8 + lc * 2;
                csum[col] = s0[nt]; csum[col + 1] = s1[nt];
            }
        }
        __syncthreads();
        if (wm == 0 && lr == 0) {
            #pragma unroll
            for (int nt = 0; nt < 8; nt++) {
                int col = wn * 64 + nt * 8 + lc * 2;
                size_t gi = (size_t)blockIdx.y * N + nbase + col;
                g_partial[gi]     = s0[nt] + csum[col];
                g_partial[gi + 1] = s1[nt] + csum[col + 1];
            }
        }
    }
}

// ---------------------------------------------------------------------------
// Prep kernels
// ---------------------------------------------------------------------------
__global__ void h_kernel(const float* __restrict__ in, __half* __restrict__ out, size_t n4) {
    size_t i = (size_t)blockIdx.x * blockDim.x + threadIdx.x;
    if (i < n4) {
        float4 v = ((const float4*)in)[i];
        ((__half2*)out)[2 * i]     = __floats2half2_rn(v.x, v.y);
        ((__half2*)out)[2 * i + 1] = __floats2half2_rn(v.z, v.w);
    }
}

// One pass over x, 64x64 tiles, float2 in / half2 out both directions:
// XR[b][i] = rn(x[b][i]) (direct, no smem);  XT[i][b] = rn(x[b][i]) (transposed).
__global__ void prep_x_kernel(const float* __restrict__ X, __half* __restrict__ XR,
                              __half* __restrict__ XT, int Bn, int INn) {
    __shared__ float t[64][65];
    const int b0 = blockIdx.x * 64, i0 = blockIdx.y * 64;
    const int tx = threadIdx.x, ty = threadIdx.y;   // 32 x 8
    #pragma unroll
    for (int r = ty; r < 64; r += 8) {
        float2 v = *(const float2*)(X + (size_t)(b0 + r) * INn + i0 + 2 * tx);
        t[r][2 * tx] = v.x; t[r][2 * tx + 1] = v.y;
        *(__half2*)(XR + (size_t)(b0 + r) * INn + i0 + 2 * tx) =
            __floats2half2_rn(v.x, v.y);
    }
    __syncthreads();
    #pragma unroll
    for (int r = ty; r < 64; r += 8) {
        __half2 h = __floats2half2_rn(t[2 * tx][r], t[2 * tx + 1][r]);
        *(__half2*)(XT + (size_t)(i0 + r) * Bn + b0 + 2 * tx) = h;
    }
}

// PT[o][b] = rn(max(O[b][o] - th[o], 0)); 64x64 tiles, float2 in / half2 out.
__global__ void pt_kernel(const float* __restrict__ O, const float* __restrict__ th,
                          __half* __restrict__ PT, int Bn, int OUTn) {
    __shared__ float t[64][65];
    __shared__ float ths[64];
    const int b0 = blockIdx.x * 64, o0 = blockIdx.y * 64;
    const int tx = threadIdx.x, ty = threadIdx.y;   // 32 x 8
    const int tid = ty * 32 + tx;
    if (tid < 64) ths[tid] = th[o0 + tid];
    #pragma unroll
    for (int r = ty; r < 64; r += 8) {
        float2 v = *(const float2*)(O + (size_t)(b0 + r) * OUTn + o0 + 2 * tx);
        t[r][2 * tx] = v.x; t[r][2 * tx + 1] = v.y;
    }
    __syncthreads();
    #pragma unroll
    for (int r = ty; r < 64; r += 8) {
        float thv = ths[r];
        __half2 h = __floats2half2_rn(fmaxf(t[2 * tx][r] - thv, 0.f),
                                      fmaxf(t[2 * tx + 1][r] - thv, 0.f));
        *(__half2*)(PT + (size_t)(o0 + r) * Bn + b0 + 2 * tx) = h;
    }
}

__global__ void thresh_kernel(const float* __restrict__ th_old,
                              float* __restrict__ th_new, int Bn, int OUTn) {
    int c = blockIdx.x * blockDim.x + threadIdx.x;
    if (c >= OUTn) return;
    float s = 0.f;
    #pragma unroll 8
    for (int p = 0; p < RSPLIT; p++) s += g_partial[p * OUTn + c];
    float act = s / (float)Bn;
    float t = th_old[c];
    th_new[c] = t + (act * act - t) / TAU_C;
}

// ---------------------------------------------------------------------------
extern "C" void kernel_launch(void* const* d_in, const int* in_sizes, int n_in,
                              void* d_out, int out_size)
{
    const float* x  = (const float*)d_in[0];
    const float* w  = (const float*)d_in[1];
    const float* th = (const float*)d_in[2];

    const int OUT = in_sizes[2];
    const int IN  = in_sizes[1] / OUT;
    const int Bn  = in_sizes[0] / IN;

    float* out    = (float*)d_out;
    float* out_O  = out;                          // B x OUT
    float* out_th = out + (size_t)Bn * OUT;       // OUT
    float* out_W  = out_th + OUT;                 // OUT x IN

    void *p;
    cudaGetSymbolAddress(&p, g_xr); __half* XR = (__half*)p;
    cudaGetSymbolAddress(&p, g_wr); __half* WR = (__half*)p;
    cudaGetSymbolAddress(&p, g_xt); __half* XT = (__half*)p;
    cudaGetSymbolAddress(&p, g_pt); __half* PT = (__half*)p;

    cudaFuncSetAttribute(gemm_mma_kernel,
                         cudaFuncAttributeMaxDynamicSharedMemorySize, SMEM_TOTAL);

    // Convert operands to fp16 (RN, unbiased; same 10-bit mantissa as tf32)
    size_t nW = (size_t)OUT * IN;
    prep_x_kernel<<<dim3(Bn / 64, IN / 64), dim3(32, 8)>>>(x, XR, XT, Bn, IN);
    h_kernel<<<(unsigned)((nW / 4 + 255) / 256), 256>>>(w, WR, nW / 4);

    // 1) O = X @ W^T   (M=B, N=OUT, K=IN), fused column partials
    dim3 g1(OUT / BN, Bn / BM);
    gemm_mma_kernel<<<g1, 128, SMEM_TOTAL>>>(XR, WR, nullptr, out_O,
                                             Bn, OUT, IN, 0.f, 0);

    // 2) threshold EMA (partials already produced by GEMM1)
    thresh_kernel<<<(OUT + 255) / 256, 256>>>(th, out_th, Bn, OUT);

    // 3) PT = relu(O - th)^T ; Wnew = W + (LR/B) * PT @ XT^T  (M=OUT, N=IN, K=B)
    pt_kernel<<<dim3(Bn / 64, OUT / 64), dim3(32, 8)>>>(out_O, out_th, PT, Bn, OUT);
    dim3 g2(IN / BN, OUT / BM);
    gemm_mma_kernel<<<g2, 128, SMEM_TOTAL>>>(PT, XT, w, out_W,
                                             OUT, IN, Bn, LR_C / (float)Bn, 1);
}

// round 15
// speedup vs baseline: 1.5852x; 1.0015x over previous
#include <cuda_runtime.h>
#include <cuda_fp16.h>
#include <cstdint>
#include <cstddef>

#define LR_C   0.001f
#define TAU_C  1000.0f

// GEMM tiling: 128x128 CTA tile, 4 warps (2x2), warp tile 64x64, fp16 BKT=64
#define BM 128
#define BN 128
#define BKT 64
#define NSTAGES 3
#define A_BYTES (BM * 128)                   // 16 KB (128 rows x 64 halves)
#define STAGE_BYTES (2 * A_BYTES)            // 32 KB
#define SMEM_TOTAL (NSTAGES * STAGE_BYTES)   // 96 KB -> 2 CTA/SM
#define RSPLIT 64                            // = DIM_B / BM

// Fixed problem shape: B=8192, IN=OUT=4096.
#define DIM_B   8192
#define DIM_IO  4096

// Scratch (__device__ globals: the sanctioned alloc-free workaround)
__device__ __half g_xr[(size_t)DIM_B * DIM_IO];   // rn(x)            B x IN
__device__ __half g_wr[(size_t)DIM_IO * DIM_IO];  // rn(w)            OUT x IN
__device__ __half g_xt[(size_t)DIM_IO * DIM_B];   // rn(x)^T          IN x B
__device__ __half g_pt[(size_t)DIM_IO * DIM_B];   // rn(relu(o-th))^T OUT x B
__device__ float  g_partial[RSPLIT * DIM_IO];

// ---------------------------------------------------------------------------
// PTX helpers (baseline sm_80+ features ONLY)
// ---------------------------------------------------------------------------
__device__ __forceinline__ uint32_t smem_u32(const void* p) {
    return (uint32_t)__cvta_generic_to_shared(p);
}

__device__ __forceinline__ void cp_async16(uint32_t s, const void* g) {
    asm volatile("cp.async.cg.shared.global [%0], [%1], 16;\n" :: "r"(s), "l"(g));
}
#define CP_COMMIT() asm volatile("cp.async.commit_group;\n" ::)
#define CP_WAIT1()  asm volatile("cp.async.wait_group 1;\n" ::: "memory")

__device__ __forceinline__ void ldsm_x4(uint32_t* r, uint32_t addr) {
    asm volatile("ldmatrix.sync.aligned.m8n8.x4.shared.b16 {%0,%1,%2,%3}, [%4];"
                 : "=r"(r[0]), "=r"(r[1]), "=r"(r[2]), "=r"(r[3]) : "r"(addr));
}

__device__ __forceinline__ uint32_t sw128(uint32_t off) {
    return off ^ ((off >> 3) & 0x70);
}

// m16n8k16 fp16 MMA, fp32 accumulate
__device__ __forceinline__ void mma_16816(float* c, const uint32_t* a,
                                          uint32_t b0, uint32_t b1) {
    asm volatile(
        "mma.sync.aligned.m16n8k16.row.col.f32.f16.f16.f32 "
        "{%0,%1,%2,%3}, {%4,%5,%6,%7}, {%8,%9}, {%0,%1,%2,%3};"
        : "+f"(c[0]), "+f"(c[1]), "+f"(c[2]), "+f"(c[3])
        : "r"(a[0]), "r"(a[1]), "r"(a[2]), "r"(a[3]), "r"(b0), "r"(b1));
}

// ---------------------------------------------------------------------------
// FP16 tensor-core GEMM: C[M,N] = A[M,K] * B[N,K]^T (both K-major half)
// mode 0: C = D, and fused per-CTA column sums -> g_partial[blockIdx.y][col]
// mode 1: C = Wold + scale * D
// SMEM layout: 128 rows x 128 bytes (64 halves = one BKT slice), SW128 swizzle.
// NOTE (R11 lesson): keep load_stage AFTER the ks-loop — issuing it early
// regressed 50% (LSU queue ahead of LDSM primes + register pressure).
// ---------------------------------------------------------------------------
__device__ __forceinline__ void load_stage(uint32_t smem_base, int stage,
                                           const __half* Ab, const __half* Bb,
                                           int K, int k0, int tid) {
    uint32_t sa = smem_base + stage * STAGE_BYTES;
    uint32_t sb = sa + A_BYTES;
    #pragma unroll
    for (int i = 0; i < 8; i++) {            // A: 128 rows x 8 x 16B chunks
        int idx = tid + i * 128;
        int row = idx >> 3, c = idx & 7;
        cp_async16(sa + sw128((uint32_t)(row * 128 + c * 16)),
                   (const char*)(Ab + (size_t)row * K + k0) + c * 16);
    }
    #pragma unroll
    for (int i = 0; i < 8; i++) {            // B: 128 rows x 8 x 16B chunks
        int idx = tid + i * 128;
        int row = idx >> 3, c = idx & 7;
        cp_async16(sb + sw128((uint32_t)(row * 128 + c * 16)),
                   (const char*)(Bb + (size_t)row * K + k0) + c * 16);
    }
}

__global__ __launch_bounds__(128, 2) void gemm_mma_kernel(
    const __half* __restrict__ A, const __half* __restrict__ Bmat,
    const float* __restrict__ Wold, float* __restrict__ C,
    int M, int N, int K, float scale, int mode)
{
    extern __shared__ char smem[];
    const uint32_t smem_base = smem_u32(smem);
    const int tid  = threadIdx.x;
    const int warp = tid >> 5, lane = tid & 31;
    const int wm = warp >> 1, wn = warp & 1;       // 2 x 2 warp grid, 64x64 each
    const int lr = lane >> 2, lc = lane & 3;

    const int mbase = blockIdx.y * BM;
    const int nbase = blockIdx.x * BN;
    const __half* Ab = A + (size_t)mbase * K;
    const __half* Bb = Bmat + (size_t)nbase * K;

    // ldmatrix addressing (128B smem rows, 16B chunks, swizzle mask (lane&7)<<4)
    const uint32_t swz_mask = (uint32_t)((lane & 7) << 4);
    const int arow = wm * 64 + ((lane >> 3) & 1) * 8 + (lane & 7);
    const uint32_t a_kb = (uint32_t)((lane >> 4) * 16);
    uint32_t a_rowoff[4];
    #pragma unroll
    for (int mt = 0; mt < 4; mt++) a_rowoff[mt] = (uint32_t)((arow + mt * 16) * 128);
    const int brow = wn * 64 + ((lane >> 4) & 1) * 8 + (lane & 7);
    const uint32_t b_kb = (uint32_t)(((lane >> 3) & 1) * 16);
    uint32_t b_rowoff[4];
    #pragma unroll
    for (int p = 0; p < 4; p++) b_rowoff[p] = (uint32_t)((brow + p * 16) * 128);

    float acc[4][8][4];                            // [mt][nt][frag]
    #pragma unroll
    for (int i = 0; i < 4; i++)
        #pragma unroll
        for (int j = 0; j < 8; j++)
            #pragma unroll
            for (int f = 0; f < 4; f++) acc[i][j][f] = 0.f;

    const int niter = K / BKT;

    load_stage(smem_base, 0, Ab, Bb, K, 0, tid);   CP_COMMIT();
    load_stage(smem_base, 1, Ab, Bb, K, BKT, tid); CP_COMMIT();

    // Fragment double buffer: load ks+1 while issuing MMAs of ks.
    uint32_t a[2][4][4], b[2][4][4];

    int buf = 0;
    for (int it = 0; it < niter; ++it) {
        CP_WAIT1();
        __syncthreads();
        uint32_t sa = smem_base + buf * STAGE_BYTES;
        uint32_t sb = sa + A_BYTES;

        // prime ks = 0
        {
            const uint32_t xa = a_kb ^ swz_mask;
            const uint32_t xb = b_kb ^ swz_mask;
            #pragma unroll
            for (int mt = 0; mt < 4; mt++) ldsm_x4(a[0][mt], sa + a_rowoff[mt] + xa);
            #pragma unroll
            for (int p = 0; p < 4; p++)    ldsm_x4(b[0][p], sb + b_rowoff[p] + xb);
        }

        #pragma unroll
        for (int ks = 0; ks < BKT / 16; ks++) {    // 4 k16-steps, 32B stride each
            const int cur = ks & 1, nxt = cur ^ 1;
            if (ks < BKT / 16 - 1) {               // prefetch next fragments
                const uint32_t xa = ((uint32_t)((ks + 1) * 32) + a_kb) ^ swz_mask;
                const uint32_t xb = ((uint32_t)((ks + 1) * 32) + b_kb) ^ swz_mask;
                #pragma unroll
                for (int mt = 0; mt < 4; mt++) ldsm_x4(a[nxt][mt], sa + a_rowoff[mt] + xa);
                #pragma unroll
                for (int p = 0; p < 4; p++)    ldsm_x4(b[nxt][p], sb + b_rowoff[p] + xb);
            }
            #pragma unroll
            for (int mt = 0; mt < 4; mt++) {
                #pragma unroll
                for (int p = 0; p < 4; p++) {
                    mma_16816(acc[mt][2 * p],     a[cur][mt], b[cur][p][0], b[cur][p][1]);
                    mma_16816(acc[mt][2 * p + 1], a[cur][mt], b[cur][p][2], b[cur][p][3]);
                }
            }
        }

        const int itn = it + 2;
        if (itn < niter)
            load_stage(smem_base, itn % NSTAGES, Ab, Bb, K, itn * BKT, tid);
        CP_COMMIT();
        buf = (buf + 1 == NSTAGES) ? 0 : buf + 1;
    }

    // Epilogue: per thread 4x8 tiles, two float2 rows each
    #pragma unroll
    for (int mt = 0; mt < 4; mt++) {
        int r0 = mbase + wm * 64 + mt * 16 + lr;
        #pragma unroll
        for (int nt = 0; nt < 8; nt++) {
            int cc = nbase + wn * 64 + nt * 8 + lc * 2;
            size_t i0 = (size_t)r0 * N + cc;
            size_t i1 = (size_t)(r0 + 8) * N + cc;
            if (mode == 0) {
                *(float2*)(C + i0) = make_float2(acc[mt][nt][0], acc[mt][nt][1]);
                *(float2*)(C + i1) = make_float2(acc[mt][nt][2], acc[mt][nt][3]);
            } else {
                float2 w0 = *(const float2*)(Wold + i0);
                float2 w1 = *(const float2*)(Wold + i1);
                w0.x += scale * acc[mt][nt][0]; w0.y += scale * acc[mt][nt][1];
                w1.x += scale * acc[mt][nt][2]; w1.y += scale * acc[mt][nt][3];
                *(float2*)(C + i0) = w0;
                *(float2*)(C + i1) = w1;
            }
        }
    }

    // Fused column partial sums for threshold EMA (mode 0 only, deterministic)
    if (mode == 0) {
        float s0[8], s1[8];
        #pragma unroll
        for (int nt = 0; nt < 8; nt++) {
            float a0 = 0.f, a1 = 0.f;
            #pragma unroll
            for (int mt = 0; mt < 4; mt++) {
                a0 += acc[mt][nt][0] + acc[mt][nt][2];
                a1 += acc[mt][nt][1] + acc[mt][nt][3];
            }
            #pragma unroll
            for (int off = 4; off <= 16; off <<= 1) {
                a0 += __shfl_xor_sync(0xffffffffu, a0, off);
                a1 += __shfl_xor_sync(0xffffffffu, a1, off);
            }
            s0[nt] = a0; s1[nt] = a1;
        }
        float* csum = (float*)smem;           // 128 floats (stage bufs done)
        __syncthreads();
        if (wm == 1 && lr == 0) {
            #pragma unroll
            for (int nt = 0; nt < 8; nt++) {
                int col = wn * 64 + nt * 8 + lc * 2;
                csum[col] = s0[nt]; csum[col + 1] = s1[nt];
            }
        }
        __syncthreads();
        if (wm == 0 && lr == 0) {
            #pragma unroll
            for (int nt = 0; nt < 8; nt++) {
                int col = wn * 64 + nt * 8 + lc * 2;
                size_t gi = (size_t)blockIdx.y * N + nbase + col;
                g_partial[gi]     = s0[nt] + csum[col];
                g_partial[gi + 1] = s1[nt] + csum[col + 1];
            }
        }
    }
}

// ---------------------------------------------------------------------------
// Prep kernels
// ---------------------------------------------------------------------------
__global__ void h_kernel(const float* __restrict__ in, __half* __restrict__ out, size_t n4) {
    size_t i = (size_t)blockIdx.x * blockDim.x + threadIdx.x;
    if (i < n4) {
        float4 v = ((const float4*)in)[i];
        ((__half2*)out)[2 * i]     = __floats2half2_rn(v.x, v.y);
        ((__half2*)out)[2 * i + 1] = __floats2half2_rn(v.z, v.w);
    }
}

// One pass over x, 64x64 tiles, float2 in / half2 out both directions:
// XR[b][i] = rn(x[b][i]) (direct, no smem);  XT[i][b] = rn(x[b][i]) (transposed).
__global__ void prep_x_kernel(const float* __restrict__ X, __half* __restrict__ XR,
                              __half* __restrict__ XT, int Bn, int INn) {
    __shared__ float t[64][65];
    const int b0 = blockIdx.x * 64, i0 = blockIdx.y * 64;
    const int tx = threadIdx.x, ty = threadIdx.y;   // 32 x 8
    #pragma unroll
    for (int r = ty; r < 64; r += 8) {
        float2 v = *(const float2*)(X + (size_t)(b0 + r) * INn + i0 + 2 * tx);
        t[r][2 * tx] = v.x; t[r][2 * tx + 1] = v.y;
        *(__half2*)(XR + (size_t)(b0 + r) * INn + i0 + 2 * tx) =
            __floats2half2_rn(v.x, v.y);
    }
    __syncthreads();
    #pragma unroll
    for (int r = ty; r < 64; r += 8) {
        __half2 h = __floats2half2_rn(t[2 * tx][r], t[2 * tx + 1][r]);
        *(__half2*)(XT + (size_t)(i0 + r) * Bn + b0 + 2 * tx) = h;
    }
}

// PT[o][b] = rn(max(O[b][o] - th[o], 0)); 64x64 tiles, float2 in / half2 out.
__global__ void pt_kernel(const float* __restrict__ O, const float* __restrict__ th,
                          __half* __restrict__ PT, int Bn, int OUTn) {
    __shared__ float t[64][65];
    __shared__ float ths[64];
    const int b0 = blockIdx.x * 64, o0 = blockIdx.y * 64;
    const int tx = threadIdx.x, ty = threadIdx.y;   // 32 x 8
    const int tid = ty * 32 + tx;
    if (tid < 64) ths[tid] = th[o0 + tid];
    #pragma unroll
    for (int r = ty; r < 64; r += 8) {
        float2 v = *(const float2*)(O + (size_t)(b0 + r) * OUTn + o0 + 2 * tx);
        t[r][2 * tx] = v.x; t[r][2 * tx + 1] = v.y;
    }
    __syncthreads();
    #pragma unroll
    for (int r = ty; r < 64; r += 8) {
        float thv = ths[r];
        __half2 h = __floats2half2_rn(fmaxf(t[2 * tx][r] - thv, 0.f),
                                      fmaxf(t[2 * tx + 1][r] - thv, 0.f));
        *(__half2*)(PT + (size_t)(o0 + r) * Bn + b0 + 2 * tx) = h;
    }
}

// Threshold EMA: grid 32, block (128,2). Each thread sums 32 rows of its
// column (deterministic fixed order), pair-combined via smem.
__global__ void thresh_kernel(const float* __restrict__ th_old,
                              float* __restrict__ th_new, int Bn, int OUTn) {
    __shared__ float red[2][128];
    const int tx = threadIdx.x, ty = threadIdx.y;
    const int c = blockIdx.x * 128 + tx;
    float s = 0.f;
    #pragma unroll 8
    for (int p = ty * 32; p < ty * 32 + 32; p++)
        s += g_partial[(size_t)p * OUTn + c];
    red[ty][tx] = s;
    __syncthreads();
    if (ty == 0) {
        float tot = red[0][tx] + red[1][tx];
        float act = tot / (float)Bn;
        float t = th_old[c];
        th_new[c] = t + (act * act - t) / TAU_C;
    }
}

// ---------------------------------------------------------------------------
extern "C" void kernel_launch(void* const* d_in, const int* in_sizes, int n_in,
                              void* d_out, int out_size)
{
    const float* x  = (const float*)d_in[0];
    const float* w  = (const float*)d_in[1];
    const float* th = (const float*)d_in[2];

    const int OUT = in_sizes[2];
    const int IN  = in_sizes[1] / OUT;
    const int Bn  = in_sizes[0] / IN;

    float* out    = (float*)d_out;
    float* out_O  = out;                          // B x OUT
    float* out_th = out + (size_t)Bn * OUT;       // OUT
    float* out_W  = out_th + OUT;                 // OUT x IN

    void *p;
    cudaGetSymbolAddress(&p, g_xr); __half* XR = (__half*)p;
    cudaGetSymbolAddress(&p, g_wr); __half* WR = (__half*)p;
    cudaGetSymbolAddress(&p, g_xt); __half* XT = (__half*)p;
    cudaGetSymbolAddress(&p, g_pt); __half* PT = (__half*)p;

    cudaFuncSetAttribute(gemm_mma_kernel,
                         cudaFuncAttributeMaxDynamicSharedMemorySize, SMEM_TOTAL);

    // Convert operands to fp16 (RN, unbiased; same 10-bit mantissa as tf32)
    size_t nW = (size_t)OUT * IN;
    prep_x_kernel<<<dim3(Bn / 64, IN / 64), dim3(32, 8)>>>(x, XR, XT, Bn, IN);
    h_kernel<<<(unsigned)((nW / 4 + 255) / 256), 256>>>(w, WR, nW / 4);

    // 1) O = X @ W^T   (M=B, N=OUT, K=IN), fused column partials
    dim3 g1(OUT / BN, Bn / BM);
    gemm_mma_kernel<<<g1, 128, SMEM_TOTAL>>>(XR, WR, nullptr, out_O,
                                             Bn, OUT, IN, 0.f, 0);

    // 2) threshold EMA (partials already produced by GEMM1)
    thresh_kernel<<<OUT / 128, dim3(128, 2)>>>(th, out_th, Bn, OUT);

    // 3) PT = relu(O - th)^T ; Wnew = W + (LR/B) * PT @ XT^T  (M=OUT, N=IN, K=B)
    pt_kernel<<<dim3(Bn / 64, OUT / 64), dim3(32, 8)>>>(out_O, out_th, PT, Bn, OUT);
    dim3 g2(IN / BN, OUT / BM);
    gemm_mma_kernel<<<g2, 128, SMEM_TOTAL>>>(PT, XT, w, out_W,
                                             OUT, IN, Bn, LR_C / (float)Bn, 1);
}

// round 16
// speedup vs baseline: 1.5860x; 1.0005x over previous
#include <cuda_runtime.h>
#include <cuda_fp16.h>
#include <cstdint>
#include <cstddef>

#define LR_C   0.001f
#define TAU_C  1000.0f

// GEMM tiling: 128x128 CTA tile, 4 warps (2x2), warp tile 64x64, fp16 BKT=64
#define BM 128
#define BN 128
#define BKT 64
#define NSTAGES 3
#define A_BYTES (BM * 128)                   // 16 KB (128 rows x 64 halves)
#define STAGE_BYTES (2 * A_BYTES)            // 32 KB
#define SMEM_TOTAL (NSTAGES * STAGE_BYTES)   // 96 KB -> 2 CTA/SM
#define RSPLIT 64                            // = DIM_B / BM

// Fixed problem shape: B=8192, IN=OUT=4096.
#define DIM_B   8192
#define DIM_IO  4096

// Scratch (__device__ globals: the sanctioned alloc-free workaround)
__device__ __half g_xr[(size_t)DIM_B * DIM_IO];   // rn(x)            B x IN
__device__ __half g_wr[(size_t)DIM_IO * DIM_IO];  // rn(w)            OUT x IN
__device__ __half g_xt[(size_t)DIM_IO * DIM_B];   // rn(x)^T          IN x B
__device__ __half g_pt[(size_t)DIM_IO * DIM_B];   // rn(relu(o-th))^T OUT x B
__device__ float  g_partial[RSPLIT * DIM_IO];

// ---------------------------------------------------------------------------
// PTX helpers (baseline sm_80+ features ONLY)
// ---------------------------------------------------------------------------
__device__ __forceinline__ uint32_t smem_u32(const void* p) {
    return (uint32_t)__cvta_generic_to_shared(p);
}

__device__ __forceinline__ void cp_async16(uint32_t s, const void* g) {
    asm volatile("cp.async.cg.shared.global [%0], [%1], 16;\n" :: "r"(s), "l"(g));
}
#define CP_COMMIT() asm volatile("cp.async.commit_group;\n" ::)
#define CP_WAIT1()  asm volatile("cp.async.wait_group 1;\n" ::: "memory")

__device__ __forceinline__ void ldsm_x4(uint32_t* r, uint32_t addr) {
    asm volatile("ldmatrix.sync.aligned.m8n8.x4.shared.b16 {%0,%1,%2,%3}, [%4];"
                 : "=r"(r[0]), "=r"(r[1]), "=r"(r[2]), "=r"(r[3]) : "r"(addr));
}

__device__ __forceinline__ uint32_t sw128(uint32_t off) {
    return off ^ ((off >> 3) & 0x70);
}

// m16n8k16 fp16 MMA, fp32 accumulate
__device__ __forceinline__ void mma_16816(float* c, const uint32_t* a,
                                          uint32_t b0, uint32_t b1) {
    asm volatile(
        "mma.sync.aligned.m16n8k16.row.col.f32.f16.f16.f32 "
        "{%0,%1,%2,%3}, {%4,%5,%6,%7}, {%8,%9}, {%0,%1,%2,%3};"
        : "+f"(c[0]), "+f"(c[1]), "+f"(c[2]), "+f"(c[3])
        : "r"(a[0]), "r"(a[1]), "r"(a[2]), "r"(a[3]), "r"(b0), "r"(b1));
}

// ---------------------------------------------------------------------------
// FP16 tensor-core GEMM: C[M,N] = A[M,K] * B[N,K]^T (both K-major half)
// mode 0: C = D, and fused per-CTA column sums -> g_partial[blockIdx.y][col]
// mode 1: C = Wold + scale * D
// SMEM layout: 128 rows x 128 bytes (64 halves = one BKT slice), SW128 swizzle.
// NOTE (R11 lesson): keep load_stage AFTER the ks-loop — issuing it early
// regressed 50% (LSU queue ahead of LDSM primes + register pressure).
// ---------------------------------------------------------------------------
__device__ __forceinline__ void load_stage(uint32_t smem_base, int stage,
                                           const __half* Ab, const __half* Bb,
                                           int K, int k0, int tid) {
    uint32_t sa = smem_base + stage * STAGE_BYTES;
    uint32_t sb = sa + A_BYTES;
    #pragma unroll
    for (int i = 0; i < 8; i++) {            // A: 128 rows x 8 x 16B chunks
        int idx = tid + i * 128;
        int row = idx >> 3, c = idx & 7;
        cp_async16(sa + sw128((uint32_t)(row * 128 + c * 16)),
                   (const char*)(Ab + (size_t)row * K + k0) + c * 16);
    }
    #pragma unroll
    for (int i = 0; i < 8; i++) {            // B: 128 rows x 8 x 16B chunks
        int idx = tid + i * 128;
        int row = idx >> 3, c = idx & 7;
        cp_async16(sb + sw128((uint32_t)(row * 128 + c * 16)),
                   (const char*)(Bb + (size_t)row * K + k0) + c * 16);
    }
}

__global__ __launch_bounds__(128, 2) void gemm_mma_kernel(
    const __half* __restrict__ A, const __half* __restrict__ Bmat,
    const float* __restrict__ Wold, float* __restrict__ C,
    int M, int N, int K, float scale, int mode)
{
    extern __shared__ char smem[];
    const uint32_t smem_base = smem_u32(smem);
    const int tid  = threadIdx.x;
    const int warp = tid >> 5, lane = tid & 31;
    const int wm = warp >> 1, wn = warp & 1;       // 2 x 2 warp grid, 64x64 each
    const int lr = lane >> 2, lc = lane & 3;

    const int mbase = blockIdx.y * BM;
    const int nbase = blockIdx.x * BN;
    const __half* Ab = A + (size_t)mbase * K;
    const __half* Bb = Bmat + (size_t)nbase * K;

    // ldmatrix addressing (128B smem rows, 16B chunks, swizzle mask (lane&7)<<4)
    const uint32_t swz_mask = (uint32_t)((lane & 7) << 4);
    const int arow = wm * 64 + ((lane >> 3) & 1) * 8 + (lane & 7);
    const uint32_t a_kb = (uint32_t)((lane >> 4) * 16);
    uint32_t a_rowoff[4];
    #pragma unroll
    for (int mt = 0; mt < 4; mt++) a_rowoff[mt] = (uint32_t)((arow + mt * 16) * 128);
    const int brow = wn * 64 + ((lane >> 4) & 1) * 8 + (lane & 7);
    const uint32_t b_kb = (uint32_t)(((lane >> 3) & 1) * 16);
    uint32_t b_rowoff[4];
    #pragma unroll
    for (int p = 0; p < 4; p++) b_rowoff[p] = (uint32_t)((brow + p * 16) * 128);

    float acc[4][8][4];                            // [mt][nt][frag]
    #pragma unroll
    for (int i = 0; i < 4; i++)
        #pragma unroll
        for (int j = 0; j < 8; j++)
            #pragma unroll
            for (int f = 0; f < 4; f++) acc[i][j][f] = 0.f;

    const int niter = K / BKT;

    load_stage(smem_base, 0, Ab, Bb, K, 0, tid);   CP_COMMIT();
    load_stage(smem_base, 1, Ab, Bb, K, BKT, tid); CP_COMMIT();

    // Fragment double buffer: load ks+1 while issuing MMAs of ks.
    uint32_t a[2][4][4], b[2][4][4];

    int buf = 0;
    for (int it = 0; it < niter; ++it) {
        CP_WAIT1();
        __syncthreads();
        uint32_t sa = smem_base + buf * STAGE_BYTES;
        uint32_t sb = sa + A_BYTES;

        // prime ks = 0
        {
            const uint32_t xa = a_kb ^ swz_mask;
            const uint32_t xb = b_kb ^ swz_mask;
            #pragma unroll
            for (int mt = 0; mt < 4; mt++) ldsm_x4(a[0][mt], sa + a_rowoff[mt] + xa);
            #pragma unroll
            for (int p = 0; p < 4; p++)    ldsm_x4(b[0][p], sb + b_rowoff[p] + xb);
        }

        #pragma unroll
        for (int ks = 0; ks < BKT / 16; ks++) {    // 4 k16-steps, 32B stride each
            const int cur = ks & 1, nxt = cur ^ 1;
            if (ks < BKT / 16 - 1) {               // prefetch next fragments
                const uint32_t xa = ((uint32_t)((ks + 1) * 32) + a_kb) ^ swz_mask;
                const uint32_t xb = ((uint32_t)((ks + 1) * 32) + b_kb) ^ swz_mask;
                #pragma unroll
                for (int mt = 0; mt < 4; mt++) ldsm_x4(a[nxt][mt], sa + a_rowoff[mt] + xa);
                #pragma unroll
                for (int p = 0; p < 4; p++)    ldsm_x4(b[nxt][p], sb + b_rowoff[p] + xb);
            }
            #pragma unroll
            for (int mt = 0; mt < 4; mt++) {
                #pragma unroll
                for (int p = 0; p < 4; p++) {
                    mma_16816(acc[mt][2 * p],     a[cur][mt], b[cur][p][0], b[cur][p][1]);
                    mma_16816(acc[mt][2 * p + 1], a[cur][mt], b[cur][p][2], b[cur][p][3]);
                }
            }
        }

        const int itn = it + 2;
        if (itn < niter)
            load_stage(smem_base, itn % NSTAGES, Ab, Bb, K, itn * BKT, tid);
        CP_COMMIT();
        buf = (buf + 1 == NSTAGES) ? 0 : buf + 1;
    }

    // Epilogue: per thread 4x8 tiles, two float2 rows each
    #pragma unroll
    for (int mt = 0; mt < 4; mt++) {
        int r0 = mbase + wm * 64 + mt * 16 + lr;
        #pragma unroll
        for (int nt = 0; nt < 8; nt++) {
            int cc = nbase + wn * 64 + nt * 8 + lc * 2;
            size_t i0 = (size_t)r0 * N + cc;
            size_t i1 = (size_t)(r0 + 8) * N + cc;
            if (mode == 0) {
                *(float2*)(C + i0) = make_float2(acc[mt][nt][0], acc[mt][nt][1]);
                *(float2*)(C + i1) = make_float2(acc[mt][nt][2], acc[mt][nt][3]);
            } else {
                float2 w0 = *(const float2*)(Wold + i0);
                float2 w1 = *(const float2*)(Wold + i1);
                w0.x += scale * acc[mt][nt][0]; w0.y += scale * acc[mt][nt][1];
                w1.x += scale * acc[mt][nt][2]; w1.y += scale * acc[mt][nt][3];
                *(float2*)(C + i0) = w0;
                *(float2*)(C + i1) = w1;
            }
        }
    }

    // Fused column partial sums for threshold EMA (mode 0 only, deterministic)
    if (mode == 0) {
        float s0[8], s1[8];
        #pragma unroll
        for (int nt = 0; nt < 8; nt++) {
            float a0 = 0.f, a1 = 0.f;
            #pragma unroll
            for (int mt = 0; mt < 4; mt++) {
                a0 += acc[mt][nt][0] + acc[mt][nt][2];
                a1 += acc[mt][nt][1] + acc[mt][nt][3];
            }
            #pragma unroll
            for (int off = 4; off <= 16; off <<= 1) {
                a0 += __shfl_xor_sync(0xffffffffu, a0, off);
                a1 += __shfl_xor_sync(0xffffffffu, a1, off);
            }
            s0[nt] = a0; s1[nt] = a1;
        }
        float* csum = (float*)smem;           // 128 floats (stage bufs done)
        __syncthreads();
        if (wm == 1 && lr == 0) {
            #pragma unroll
            for (int nt = 0; nt < 8; nt++) {
                int col = wn * 64 + nt * 8 + lc * 2;
                csum[col] = s0[nt]; csum[col + 1] = s1[nt];
            }
        }
        __syncthreads();
        if (wm == 0 && lr == 0) {
            #pragma unroll
            for (int nt = 0; nt < 8; nt++) {
                int col = wn * 64 + nt * 8 + lc * 2;
                size_t gi = (size_t)blockIdx.y * N + nbase + col;
                g_partial[gi]     = s0[nt] + csum[col];
                g_partial[gi + 1] = s1[nt] + csum[col + 1];
            }
        }
    }
}

// ---------------------------------------------------------------------------
// Prep kernels
// ---------------------------------------------------------------------------
__global__ void h_kernel(const float* __restrict__ in, __half* __restrict__ out, size_t n4) {
    size_t i = (size_t)blockIdx.x * blockDim.x + threadIdx.x;
    if (i < n4) {
        float4 v = ((const float4*)in)[i];
        ((__half2*)out)[2 * i]     = __floats2half2_rn(v.x, v.y);
        ((__half2*)out)[2 * i + 1] = __floats2half2_rn(v.z, v.w);
    }
}

// One pass over x, 64x64 tiles, float2 in / half2 out both directions:
// XR[b][i] = rn(x[b][i]) (direct, no smem);  XT[i][b] = rn(x[b][i]) (transposed).
__global__ void prep_x_kernel(const float* __restrict__ X, __half* __restrict__ XR,
                              __half* __restrict__ XT, int Bn, int INn) {
    __shared__ float t[64][65];
    const int b0 = blockIdx.x * 64, i0 = blockIdx.y * 64;
    const int tx = threadIdx.x, ty = threadIdx.y;   // 32 x 8
    #pragma unroll
    for (int r = ty; r < 64; r += 8) {
        float2 v = *(const float2*)(X + (size_t)(b0 + r) * INn + i0 + 2 * tx);
        t[r][2 * tx] = v.x; t[r][2 * tx + 1] = v.y;
        *(__half2*)(XR + (size_t)(b0 + r) * INn + i0 + 2 * tx) =
            __floats2half2_rn(v.x, v.y);
    }
    __syncthreads();
    #pragma unroll
    for (int r = ty; r < 64; r += 8) {
        __half2 h = __floats2half2_rn(t[2 * tx][r], t[2 * tx + 1][r]);
        *(__half2*)(XT + (size_t)(i0 + r) * Bn + b0 + 2 * tx) = h;
    }
}

// Fused threshold EMA + PT build, FULL parallelism (R12 lesson: never serialize).
// Grid (Bn/64, OUT/64) — one 64x64 tile per block, same as the fast pt_kernel.
// Each block independently computes th_new for its 64 columns from g_partial
// (1 MB, L2-resident; deterministic fixed-order sum, identical in every block).
// Blocks with blockIdx.x == 0 write out_th.
__global__ void pt_kernel(const float* __restrict__ O, const float* __restrict__ th_old,
                          float* __restrict__ th_new, __half* __restrict__ PT,
                          int Bn, int OUTn) {
    __shared__ float t[64][65];
    __shared__ float red[4][64];
    __shared__ float ths[64];
    const int b0 = blockIdx.x * 64, o0 = blockIdx.y * 64;
    const int tx = threadIdx.x, ty = threadIdx.y;   // 32 x 8
    const int tid = ty * 32 + tx;                   // 0..255

    // --- threshold for columns o0..o0+63 (4 threads per column x 16 rows) ---
    {
        const int col = tid & 63;      // 0..63
        const int q   = tid >> 6;      // 0..3
        float s = 0.f;
        #pragma unroll
        for (int p = q * 16; p < q * 16 + 16; p++)
            s += g_partial[(size_t)p * OUTn + o0 + col];
        red[q][col] = s;
    }
    __syncthreads();
    if (tid < 64) {
        float tot = red[0][tid] + red[1][tid] + red[2][tid] + red[3][tid];
        float act = tot / (float)Bn;
        float tv = th_old[o0 + tid];
        float thn = tv + (act * act - tv) / TAU_C;
        ths[tid] = thn;
        if (blockIdx.x == 0) th_new[o0 + tid] = thn;
    }

    // --- load O tile (overlaps with threshold compute; sync below covers both)
    #pragma unroll
    for (int r = ty; r < 64; r += 8) {
        float2 v = *(const float2*)(O + (size_t)(b0 + r) * OUTn + o0 + 2 * tx);
        t[r][2 * tx] = v.x; t[r][2 * tx + 1] = v.y;
    }
    __syncthreads();

    // --- relu-transpose ---
    #pragma unroll
    for (int r = ty; r < 64; r += 8) {
        float thv = ths[r];
        __half2 h = __floats2half2_rn(fmaxf(t[2 * tx][r] - thv, 0.f),
                                      fmaxf(t[2 * tx + 1][r] - thv, 0.f));
        *(__half2*)(PT + (size_t)(o0 + r) * Bn + b0 + 2 * tx) = h;
    }
}

// ---------------------------------------------------------------------------
extern "C" void kernel_launch(void* const* d_in, const int* in_sizes, int n_in,
                              void* d_out, int out_size)
{
    const float* x  = (const float*)d_in[0];
    const float* w  = (const float*)d_in[1];
    const float* th = (const float*)d_in[2];

    const int OUT = in_sizes[2];
    const int IN  = in_sizes[1] / OUT;
    const int Bn  = in_sizes[0] / IN;

    float* out    = (float*)d_out;
    float* out_O  = out;                          // B x OUT
    float* out_th = out + (size_t)Bn * OUT;       // OUT
    float* out_W  = out_th + OUT;                 // OUT x IN

    void *p;
    cudaGetSymbolAddress(&p, g_xr); __half* XR = (__half*)p;
    cudaGetSymbolAddress(&p, g_wr); __half* WR = (__half*)p;
    cudaGetSymbolAddress(&p, g_xt); __half* XT = (__half*)p;
    cudaGetSymbolAddress(&p, g_pt); __half* PT = (__half*)p;

    cudaFuncSetAttribute(gemm_mma_kernel,
                         cudaFuncAttributeMaxDynamicSharedMemorySize, SMEM_TOTAL);

    // Convert operands to fp16 (RN, unbiased; same 10-bit mantissa as tf32)
    size_t nW = (size_t)OUT * IN;
    prep_x_kernel<<<dim3(Bn / 64, IN / 64), dim3(32, 8)>>>(x, XR, XT, Bn, IN);
    h_kernel<<<(unsigned)((nW / 4 + 255) / 256), 256>>>(w, WR, nW / 4);

    // 1) O = X @ W^T   (M=B, N=OUT, K=IN), fused column partials
    dim3 g1(OUT / BN, Bn / BM);
    gemm_mma_kernel<<<g1, 128, SMEM_TOTAL>>>(XR, WR, nullptr, out_O,
                                             Bn, OUT, IN, 0.f, 0);

    // 2+3a) fused threshold EMA + PT = relu(O - th)^T (full-parallel tiles)
    pt_kernel<<<dim3(Bn / 64, OUT / 64), dim3(32, 8)>>>(out_O, th, out_th, PT,
                                                        Bn, OUT);

    // 3b) Wnew = W + (LR/B) * PT @ XT^T  (M=OUT, N=IN, K=B)
    dim3 g2(IN / BN, OUT / BM);
    gemm_mma_kernel<<<g2, 128, SMEM_TOTAL>>>(PT, XT, w, out_W,
                                             OUT, IN, Bn, LR_C / (float)Bn, 1);
}

// round 17
// speedup vs baseline: 1.6028x; 1.0106x over previous
#include <cuda_runtime.h>
#include <cuda_fp16.h>
#include <cstdint>
#include <cstddef>

#define LR_C   0.001f
#define TAU_C  1000.0f

// GEMM tiling: 128x128 CTA tile, 4 warps (2x2), warp tile 64x64, fp16 BKT=64
#define BM 128
#define BN 128
#define BKT 64
#define NSTAGES 3
#define A_BYTES (BM * 128)                   // 16 KB (128 rows x 64 halves)
#define STAGE_BYTES (2 * A_BYTES)            // 32 KB
#define SMEM_TOTAL (NSTAGES * STAGE_BYTES)   // 96 KB -> 2 CTA/SM
#define RSPLIT 64                            // = DIM_B / BM

// Fixed problem shape: B=8192, IN=OUT=4096.
#define DIM_B   8192
#define DIM_IO  4096

// Scratch (__device__ globals: the sanctioned alloc-free workaround)
__device__ __half g_xr[(size_t)DIM_B * DIM_IO];   // rn(x)            B x IN
__device__ __half g_wr[(size_t)DIM_IO * DIM_IO];  // rn(w)            OUT x IN
__device__ __half g_xt[(size_t)DIM_IO * DIM_B];   // rn(x)^T          IN x B
__device__ __half g_pt[(size_t)DIM_IO * DIM_B];   // rn(relu(o-th))^T OUT x B
__device__ float  g_partial[RSPLIT * DIM_IO];

// ---------------------------------------------------------------------------
// PTX helpers (baseline sm_80+ features ONLY)
// ---------------------------------------------------------------------------
__device__ __forceinline__ uint32_t smem_u32(const void* p) {
    return (uint32_t)__cvta_generic_to_shared(p);
}

__device__ __forceinline__ void cp_async16(uint32_t s, const void* g) {
    asm volatile("cp.async.cg.shared.global [%0], [%1], 16;\n" :: "r"(s), "l"(g));
}
#define CP_COMMIT() asm volatile("cp.async.commit_group;\n" ::)
#define CP_WAIT1()  asm volatile("cp.async.wait_group 1;\n" ::: "memory")

__device__ __forceinline__ void ldsm_x4(uint32_t* r, uint32_t addr) {
    asm volatile("ldmatrix.sync.aligned.m8n8.x4.shared.b16 {%0,%1,%2,%3}, [%4];"
                 : "=r"(r[0]), "=r"(r[1]), "=r"(r[2]), "=r"(r[3]) : "r"(addr));
}

__device__ __forceinline__ uint32_t sw128(uint32_t off) {
    return off ^ ((off >> 3) & 0x70);
}

// m16n8k16 fp16 MMA, fp32 accumulate
__device__ __forceinline__ void mma_16816(float* c, const uint32_t* a,
                                          uint32_t b0, uint32_t b1) {
    asm volatile(
        "mma.sync.aligned.m16n8k16.row.col.f32.f16.f16.f32 "
        "{%0,%1,%2,%3}, {%4,%5,%6,%7}, {%8,%9}, {%0,%1,%2,%3};"
        : "+f"(c[0]), "+f"(c[1]), "+f"(c[2]), "+f"(c[3])
        : "r"(a[0]), "r"(a[1]), "r"(a[2]), "r"(a[3]), "r"(b0), "r"(b1));
}

// ---------------------------------------------------------------------------
// FP16 tensor-core GEMM: C[M,N] = A[M,K] * B[N,K]^T (both K-major half)
// mode 0: C = D, and fused per-CTA column sums -> g_partial[blockIdx.y][col]
// mode 1: C = Wold + scale * D
// SMEM layout: 128 rows x 128 bytes (64 halves = one BKT slice), SW128 swizzle.
// NOTE (R11 lesson): keep load_stage AFTER the ks-loop — issuing it early
// regressed 50% (LSU queue ahead of LDSM primes + register pressure).
// ---------------------------------------------------------------------------
__device__ __forceinline__ void load_stage(uint32_t smem_base, int stage,
                                           const __half* Ab, const __half* Bb,
                                           int K, int k0, int tid) {
    uint32_t sa = smem_base + stage * STAGE_BYTES;
    uint32_t sb = sa + A_BYTES;
    #pragma unroll
    for (int i = 0; i < 8; i++) {            // A: 128 rows x 8 x 16B chunks
        int idx = tid + i * 128;
        int row = idx >> 3, c = idx & 7;
        cp_async16(sa + sw128((uint32_t)(row * 128 + c * 16)),
                   (const char*)(Ab + (size_t)row * K + k0) + c * 16);
    }
    #pragma unroll
    for (int i = 0; i < 8; i++) {            // B: 128 rows x 8 x 16B chunks
        int idx = tid + i * 128;
        int row = idx >> 3, c = idx & 7;
        cp_async16(sb + sw128((uint32_t)(row * 128 + c * 16)),
                   (const char*)(Bb + (size_t)row * K + k0) + c * 16);
    }
}

__global__ __launch_bounds__(128, 2) void gemm_mma_kernel(
    const __half* __restrict__ A, const __half* __restrict__ Bmat,
    const float* __restrict__ Wold, float* __restrict__ C,
    int M, int N, int K, float scale, int mode)
{
    extern __shared__ char smem[];
    const uint32_t smem_base = smem_u32(smem);
    const int tid  = threadIdx.x;
    const int warp = tid >> 5, lane = tid & 31;
    const int wm = warp >> 1, wn = warp & 1;       // 2 x 2 warp grid, 64x64 each
    const int lr = lane >> 2, lc = lane & 3;

    const int mbase = blockIdx.y * BM;
    const int nbase = blockIdx.x * BN;
    const __half* Ab = A + (size_t)mbase * K;
    const __half* Bb = Bmat + (size_t)nbase * K;

    // ldmatrix addressing (128B smem rows, 16B chunks, swizzle mask (lane&7)<<4)
    const uint32_t swz_mask = (uint32_t)((lane & 7) << 4);
    const int arow = wm * 64 + ((lane >> 3) & 1) * 8 + (lane & 7);
    const uint32_t a_kb = (uint32_t)((lane >> 4) * 16);
    uint32_t a_rowoff[4];
    #pragma unroll
    for (int mt = 0; mt < 4; mt++) a_rowoff[mt] = (uint32_t)((arow + mt * 16) * 128);
    const int brow = wn * 64 + ((lane >> 4) & 1) * 8 + (lane & 7);
    const uint32_t b_kb = (uint32_t)(((lane >> 3) & 1) * 16);
    uint32_t b_rowoff[4];
    #pragma unroll
    for (int p = 0; p < 4; p++) b_rowoff[p] = (uint32_t)((brow + p * 16) * 128);

    float acc[4][8][4];                            // [mt][nt][frag]
    #pragma unroll
    for (int i = 0; i < 4; i++)
        #pragma unroll
        for (int j = 0; j < 8; j++)
            #pragma unroll
            for (int f = 0; f < 4; f++) acc[i][j][f] = 0.f;

    const int niter = K / BKT;

    load_stage(smem_base, 0, Ab, Bb, K, 0, tid);   CP_COMMIT();
    load_stage(smem_base, 1, Ab, Bb, K, BKT, tid); CP_COMMIT();

    // Fragment double buffer: load ks+1 while issuing MMAs of ks.
    uint32_t a[2][4][4], b[2][4][4];

    int buf = 0;
    for (int it = 0; it < niter; ++it) {
        CP_WAIT1();
        __syncthreads();
        uint32_t sa = smem_base + buf * STAGE_BYTES;
        uint32_t sb = sa + A_BYTES;

        // prime ks = 0
        {
            const uint32_t xa = a_kb ^ swz_mask;
            const uint32_t xb = b_kb ^ swz_mask;
            #pragma unroll
            for (int mt = 0; mt < 4; mt++) ldsm_x4(a[0][mt], sa + a_rowoff[mt] + xa);
            #pragma unroll
            for (int p = 0; p < 4; p++)    ldsm_x4(b[0][p], sb + b_rowoff[p] + xb);
        }

        #pragma unroll
        for (int ks = 0; ks < BKT / 16; ks++) {    // 4 k16-steps, 32B stride each
            const int cur = ks & 1, nxt = cur ^ 1;
            if (ks < BKT / 16 - 1) {               // prefetch next fragments
                const uint32_t xa = ((uint32_t)((ks + 1) * 32) + a_kb) ^ swz_mask;
                const uint32_t xb = ((uint32_t)((ks + 1) * 32) + b_kb) ^ swz_mask;
                #pragma unroll
                for (int mt = 0; mt < 4; mt++) ldsm_x4(a[nxt][mt], sa + a_rowoff[mt] + xa);
                #pragma unroll
                for (int p = 0; p < 4; p++)    ldsm_x4(b[nxt][p], sb + b_rowoff[p] + xb);
            }
            #pragma unroll
            for (int mt = 0; mt < 4; mt++) {
                #pragma unroll
                for (int p = 0; p < 4; p++) {
                    mma_16816(acc[mt][2 * p],     a[cur][mt], b[cur][p][0], b[cur][p][1]);
                    mma_16816(acc[mt][2 * p + 1], a[cur][mt], b[cur][p][2], b[cur][p][3]);
                }
            }
        }

        const int itn = it + 2;
        if (itn < niter)
            load_stage(smem_base, itn % NSTAGES, Ab, Bb, K, itn * BKT, tid);
        CP_COMMIT();
        buf = (buf + 1 == NSTAGES) ? 0 : buf + 1;
    }

    // Epilogue: per thread 4x8 tiles, two float2 rows each
    #pragma unroll
    for (int mt = 0; mt < 4; mt++) {
        int r0 = mbase + wm * 64 + mt * 16 + lr;
        #pragma unroll
        for (int nt = 0; nt < 8; nt++) {
            int cc = nbase + wn * 64 + nt * 8 + lc * 2;
            size_t i0 = (size_t)r0 * N + cc;
            size_t i1 = (size_t)(r0 + 8) * N + cc;
            if (mode == 0) {
                *(float2*)(C + i0) = make_float2(acc[mt][nt][0], acc[mt][nt][1]);
                *(float2*)(C + i1) = make_float2(acc[mt][nt][2], acc[mt][nt][3]);
            } else {
                float2 w0 = *(const float2*)(Wold + i0);
                float2 w1 = *(const float2*)(Wold + i1);
                w0.x += scale * acc[mt][nt][0]; w0.y += scale * acc[mt][nt][1];
                w1.x += scale * acc[mt][nt][2]; w1.y += scale * acc[mt][nt][3];
                *(float2*)(C + i0) = w0;
                *(float2*)(C + i1) = w1;
            }
        }
    }

    // Fused column partial sums for threshold EMA (mode 0 only, deterministic)
    if (mode == 0) {
        float s0[8], s1[8];
        #pragma unroll
        for (int nt = 0; nt < 8; nt++) {
            float a0 = 0.f, a1 = 0.f;
            #pragma unroll
            for (int mt = 0; mt < 4; mt++) {
                a0 += acc[mt][nt][0] + acc[mt][nt][2];
                a1 += acc[mt][nt][1] + acc[mt][nt][3];
            }
            #pragma unroll
            for (int off = 4; off <= 16; off <<= 1) {
                a0 += __shfl_xor_sync(0xffffffffu, a0, off);
                a1 += __shfl_xor_sync(0xffffffffu, a1, off);
            }
            s0[nt] = a0; s1[nt] = a1;
        }
        float* csum = (float*)smem;           // 128 floats (stage bufs done)
        __syncthreads();
        if (wm == 1 && lr == 0) {
            #pragma unroll
            for (int nt = 0; nt < 8; nt++) {
                int col = wn * 64 + nt * 8 + lc * 2;
                csum[col] = s0[nt]; csum[col + 1] = s1[nt];
            }
        }
        __syncthreads();
        if (wm == 0 && lr == 0) {
            #pragma unroll
            for (int nt = 0; nt < 8; nt++) {
                int col = wn * 64 + nt * 8 + lc * 2;
                size_t gi = (size_t)blockIdx.y * N + nbase + col;
                g_partial[gi]     = s0[nt] + csum[col];
                g_partial[gi + 1] = s1[nt] + csum[col + 1];
            }
        }
    }
}

// ---------------------------------------------------------------------------
// Prep kernels
// ---------------------------------------------------------------------------
__global__ void h_kernel(const float* __restrict__ in, __half* __restrict__ out, size_t n4) {
    size_t i = (size_t)blockIdx.x * blockDim.x + threadIdx.x;
    if (i < n4) {
        float4 v = ((const float4*)in)[i];
        ((__half2*)out)[2 * i]     = __floats2half2_rn(v.x, v.y);
        ((__half2*)out)[2 * i + 1] = __floats2half2_rn(v.z, v.w);
    }
}

// One pass over x, 64x64 tiles. Convert to half BEFORE the smem store
// (bit-identical result, half the smem traffic). Stride 65 halves makes both
// the scalar stores and the transposed scalar reads bank-conflict-free.
__global__ void prep_x_kernel(const float* __restrict__ X, __half* __restrict__ XR,
                              __half* __restrict__ XT, int Bn, int INn) {
    __shared__ __half t[64 * 65];
    const int b0 = blockIdx.x * 64, i0 = blockIdx.y * 64;
    const int tx = threadIdx.x, ty = threadIdx.y;   // 32 x 8
    #pragma unroll
    for (int r = ty; r < 64; r += 8) {
        float2 v = *(const float2*)(X + (size_t)(b0 + r) * INn + i0 + 2 * tx);
        __half h0 = __float2half_rn(v.x);
        __half h1 = __float2half_rn(v.y);
        t[r * 65 + 2 * tx]     = h0;
        t[r * 65 + 2 * tx + 1] = h1;
        *(__half2*)(XR + (size_t)(b0 + r) * INn + i0 + 2 * tx) =
            __halves2half2(h0, h1);
    }
    __syncthreads();
    #pragma unroll
    for (int r = ty; r < 64; r += 8) {
        __half2 h = __halves2half2(t[(2 * tx) * 65 + r], t[(2 * tx + 1) * 65 + r]);
        *(__half2*)(XT + (size_t)(i0 + r) * Bn + b0 + 2 * tx) = h;
    }
}

// Fused threshold EMA + PT build, full parallelism (R12 lesson), half-smem
// transpose. relu+convert happen at LOAD time (o is the contiguous coord
// there, so ths is available) — bit-identical PT, half the smem bytes.
// Each block computes th_new for its 64 columns from g_partial
// (deterministic fixed-order sum, identical in every block); bx==0 writes th.
__global__ void pt_kernel(const float* __restrict__ O, const float* __restrict__ th_old,
                          float* __restrict__ th_new, __half* __restrict__ PT,
                          int Bn, int OUTn) {
    __shared__ __half t[64 * 65];
    __shared__ float red[4][64];
    __shared__ float ths[64];
    const int b0 = blockIdx.x * 64, o0 = blockIdx.y * 64;
    const int tx = threadIdx.x, ty = threadIdx.y;   // 32 x 8
    const int tid = ty * 32 + tx;                   // 0..255

    // threshold partials (4 threads per column x 16 rows each)
    {
        const int col = tid & 63;
        const int q   = tid >> 6;
        float s = 0.f;
        #pragma unroll
        for (int p = q * 16; p < q * 16 + 16; p++)
            s += g_partial[(size_t)p * OUTn + o0 + col];
        red[q][col] = s;
    }

    // stage O into registers (overlaps the reduction; no ths needed yet)
    float2 v[8];
    #pragma unroll
    for (int i = 0; i < 8; i++) {
        int r = ty + i * 8;
        v[i] = *(const float2*)(O + (size_t)(b0 + r) * OUTn + o0 + 2 * tx);
    }

    __syncthreads();
    if (tid < 64) {
        float tot = red[0][tid] + red[1][tid] + red[2][tid] + red[3][tid];
        float act = tot / (float)Bn;
        float tv = th_old[o0 + tid];
        float thn = tv + (act * act - tv) / TAU_C;
        ths[tid] = thn;
        if (blockIdx.x == 0) th_new[o0 + tid] = thn;
    }
    __syncthreads();

    // relu + convert at load orientation, store half into transpose buffer
    const float th0 = ths[2 * tx], th1 = ths[2 * tx + 1];
    #pragma unroll
    for (int i = 0; i < 8; i++) {
        int r = ty + i * 8;
        t[r * 65 + 2 * tx]     = __float2half_rn(fmaxf(v[i].x - th0, 0.f));
        t[r * 65 + 2 * tx + 1] = __float2half_rn(fmaxf(v[i].y - th1, 0.f));
    }
    __syncthreads();

    // transposed half2 writes
    #pragma unroll
    for (int r = ty; r < 64; r += 8) {
        __half2 h = __halves2half2(t[(2 * tx) * 65 + r], t[(2 * tx + 1) * 65 + r]);
        *(__half2*)(PT + (size_t)(o0 + r) * Bn + b0 + 2 * tx) = h;
    }
}

// ---------------------------------------------------------------------------
extern "C" void kernel_launch(void* const* d_in, const int* in_sizes, int n_in,
                              void* d_out, int out_size)
{
    const float* x  = (const float*)d_in[0];
    const float* w  = (const float*)d_in[1];
    const float* th = (const float*)d_in[2];

    const int OUT = in_sizes[2];
    const int IN  = in_sizes[1] / OUT;
    const int Bn  = in_sizes[0] / IN;

    float* out    = (float*)d_out;
    float* out_O  = out;                          // B x OUT
    float* out_th = out + (size_t)Bn * OUT;       // OUT
    float* out_W  = out_th + OUT;                 // OUT x IN

    void *p;
    cudaGetSymbolAddress(&p, g_xr); __half* XR = (__half*)p;
    cudaGetSymbolAddress(&p, g_wr); __half* WR = (__half*)p;
    cudaGetSymbolAddress(&p, g_xt); __half* XT = (__half*)p;
    cudaGetSymbolAddress(&p, g_pt); __half* PT = (__half*)p;

    cudaFuncSetAttribute(gemm_mma_kernel,
                         cudaFuncAttributeMaxDynamicSharedMemorySize, SMEM_TOTAL);

    // Convert operands to fp16 (RN, unbiased; same 10-bit mantissa as tf32)
    size_t nW = (size_t)OUT * IN;
    prep_x_kernel<<<dim3(Bn / 64, IN / 64), dim3(32, 8)>>>(x, XR, XT, Bn, IN);
    h_kernel<<<(unsigned)((nW / 4 + 255) / 256), 256>>>(w, WR, nW / 4);

    // 1) O = X @ W^T   (M=B, N=OUT, K=IN), fused column partials
    dim3 g1(OUT / BN, Bn / BM);
    gemm_mma_kernel<<<g1, 128, SMEM_TOTAL>>>(XR, WR, nullptr, out_O,
                                             Bn, OUT, IN, 0.f, 0);

    // 2+3a) fused threshold EMA + PT = relu(O - th)^T (full-parallel tiles)
    pt_kernel<<<dim3(Bn / 64, OUT / 64), dim3(32, 8)>>>(out_O, th, out_th, PT,
                                                        Bn, OUT);

    // 3b) Wnew = W + (LR/B) * PT @ XT^T  (M=OUT, N=IN, K=B)
    dim3 g2(IN / BN, OUT / BM);
    gemm_mma_kernel<<<g2, 128, SMEM_TOTAL>>>(PT, XT, w, out_W,
                                             OUT, IN, Bn, LR_C / (float)Bn, 1);
}